// round 8
// baseline (speedup 1.0000x reference)
#include <cuda_runtime.h>
#include <cuda_fp16.h>
#include <cuda_bf16.h>

#define NN 100000
#define EE 1600000
#define GG 256
#define HH 64
#define BN_EPS 1e-5f

// ---------------- scratch (device globals; zero-initialized at load) ----------------
__device__ int     g_deg[NN];          // re-zeroed by k_csr each run
__device__ int     g_total;            // re-zeroed by k_csr each run
__device__ float   g_dinv[NN];
__device__ float4  g_xs[NN];           // dinv * x (3-wide, w=0)
__device__ __half2 g_hsh[NN * 32];     // (x @ W) * dinv, fp16 (64 dims = 32 half2)
__device__ float   g_x[NN * HH];       // layer activations (fp32)
__device__ int     g_rowptr[NN];
__device__ int     g_rowend[NN];
__device__ int     g_cursor[NN];
__device__ int     g_csrsrc[EE];
__device__ float   g_gsum[GG * HH];    // re-zeroed by k_mlp each run
__device__ int     g_gmax[GG * HH];    // re-zeroed by k_mlp each run
__device__ float   g_gcnt[GG];         // re-zeroed by k_mlp each run

// ---------------- degree histogram (by dst) ----------------
__global__ void k_deg(const int* __restrict__ ei) {
    int e = blockIdx.x * blockDim.x + threadIdx.x;
    if (e < EE) atomicAdd(&g_deg[ei[EE + e]], 1);
}

// ---------------- CSR slot allocation: warp-aggregated atomic, no scan ----------------
__global__ void k_alloc(const float* __restrict__ x) {
    int i = blockIdx.x * blockDim.x + threadIdx.x;
    int lane = threadIdx.x & 31;
    int d = (i < NN) ? g_deg[i] : 0;
    int incl = d;
#pragma unroll
    for (int off = 1; off < 32; off <<= 1) {
        int v = __shfl_up_sync(0xffffffffu, incl, off);
        if (lane >= off) incl += v;
    }
    int total = __shfl_sync(0xffffffffu, incl, 31);
    int base = 0;
    if (lane == 31) base = atomicAdd(&g_total, total);
    base = __shfl_sync(0xffffffffu, base, 31);
    int excl = base + incl - d;
    if (i < NN) {
        g_rowptr[i] = excl;
        g_rowend[i] = excl + d;
        g_cursor[i] = excl;
        float dv = rsqrtf((float)d + 1.0f);
        g_dinv[i] = dv;
        g_xs[i] = make_float4(x[i * 3] * dv, x[i * 3 + 1] * dv, x[i * 3 + 2] * dv, 0.f);
    }
}

// ---------------- CSR fill (+ cleanup of deg/total for next replay) ----------------
__global__ void k_csr(const int* __restrict__ ei) {
    int e = blockIdx.x * blockDim.x + threadIdx.x;
    if (e < NN) g_deg[e] = 0;
    if (e == 0) g_total = 0;
    if (e < EE) {
        int s = ei[e];
        int d = ei[EE + e];
        int p = atomicAdd(&g_cursor[d], 1);
        g_csrsrc[p] = s;
    }
}

// ---------------- layer 0 fused: parallel input-space gather + GEMM + BN + ReLU ----------------
// 64 nodes/block; gather phase: 4 lanes per node (every 4th edge), shfl_xor reduce.
__global__ void __launch_bounds__(256) k_layer0(const float* __restrict__ W0,
        const float* __restrict__ b, const float* __restrict__ gm,
        const float* __restrict__ be, const float* __restrict__ rm,
        const float* __restrict__ rv) {
    __shared__ float sW[192];
    __shared__ float sxa[64][3];
    int t = threadIdx.x;
    int lane = t & 31;
    int warp = t >> 5;
    if (t < 192) sW[t] = W0[t];

    int nl = warp * 8 + (lane >> 2);   // 0..63 local node
    int sub = lane & 3;
    int n = blockIdx.x * 64 + nl;

    float ax = 0.f, ay = 0.f, az = 0.f;
    if (n < NN) {
        int beg = g_rowptr[n], end = g_rowend[n];
        const int* __restrict__ idx = g_csrsrc;
        for (int k = beg + sub; k < end; k += 4) {
            float4 a = g_xs[idx[k]];
            ax += a.x; ay += a.y; az += a.z;
        }
    }
    // reduce across the 4 sub-lanes
    ax += __shfl_xor_sync(0xffffffffu, ax, 1);
    ay += __shfl_xor_sync(0xffffffffu, ay, 1);
    az += __shfl_xor_sync(0xffffffffu, az, 1);
    ax += __shfl_xor_sync(0xffffffffu, ax, 2);
    ay += __shfl_xor_sync(0xffffffffu, ay, 2);
    az += __shfl_xor_sync(0xffffffffu, az, 2);
    if (sub == 0 && n < NN) {
        float4 self = g_xs[n];
        float dv = g_dinv[n];
        sxa[nl][0] = (ax + self.x) * dv;
        sxa[nl][1] = (ay + self.y) * dv;
        sxa[nl][2] = (az + self.z) * dv;
    }
    __syncthreads();

    // phase 2: GEMM 3->64 + BN + ReLU; 16 nodes x 16 float4-cols per round, 4 rounds
    int q = t & 15;
    int j = q * 4;
    float4 sc, sh;
    sc.x = gm[j] * rsqrtf(rv[j] + BN_EPS);
    sc.y = gm[j + 1] * rsqrtf(rv[j + 1] + BN_EPS);
    sc.z = gm[j + 2] * rsqrtf(rv[j + 2] + BN_EPS);
    sc.w = gm[j + 3] * rsqrtf(rv[j + 3] + BN_EPS);
    sh.x = (b[j] - rm[j]) * sc.x + be[j];
    sh.y = (b[j + 1] - rm[j + 1]) * sc.y + be[j + 1];
    sh.z = (b[j + 2] - rm[j + 2]) * sc.z + be[j + 2];
    sh.w = (b[j + 3] - rm[j + 3]) * sc.w + be[j + 3];
    float w0x = sW[j],       w0y = sW[j + 1],       w0z = sW[j + 2],       w0w = sW[j + 3];
    float w1x = sW[64 + j],  w1y = sW[64 + j + 1],  w1z = sW[64 + j + 2],  w1w = sW[64 + j + 3];
    float w2x = sW[128 + j], w2y = sW[128 + j + 1], w2z = sW[128 + j + 2], w2w = sW[128 + j + 3];
#pragma unroll
    for (int r = 0; r < 4; r++) {
        int nl2 = r * 16 + (t >> 4);
        int gn = blockIdx.x * 64 + nl2;
        if (gn >= NN) break;
        float a0 = sxa[nl2][0], a1 = sxa[nl2][1], a2 = sxa[nl2][2];
        float4 o;
        o.x = fmaxf(fmaf(a0 * w0x + a1 * w1x + a2 * w2x, sc.x, sh.x), 0.f);
        o.y = fmaxf(fmaf(a0 * w0y + a1 * w1y + a2 * w2y, sc.y, sh.y), 0.f);
        o.z = fmaxf(fmaf(a0 * w0z + a1 * w1z + a2 * w2z, sc.z, sh.z), 0.f);
        o.w = fmaxf(fmaf(a0 * w0w + a1 * w1w + a2 * w2w, sc.w, sh.w), 0.f);
        ((float4*)g_x)[gn * 16 + q] = o;
    }
}

// ---------------- layers 1,2 GEMM: hs = (g_x @ W) * dinv ; packed f32x2, fp16 out ----------------
__global__ void __launch_bounds__(256) k_mmA(const float* __restrict__ W) {
    __shared__ float2 sWd[64 * 32];
    __shared__ float2 sx2[64 * 64];
    int t = threadIdx.x;
    int nbase = blockIdx.x * 64;
#pragma unroll
    for (int i = t; i < 2048; i += 256) sWd[i] = ((const float2*)W)[i];
#pragma unroll
    for (int i = t; i < 1024; i += 256) {
        int n = i >> 4, q = i & 15;
        int gn = nbase + n;
        float4 v = (gn < NN) ? ((const float4*)g_x)[gn * 16 + q]
                             : make_float4(0.f, 0.f, 0.f, 0.f);
        float2* dst = sx2 + n * 64 + q * 4;
        dst[0] = make_float2(v.x, v.x);
        dst[1] = make_float2(v.y, v.y);
        dst[2] = make_float2(v.z, v.z);
        dst[3] = make_float2(v.w, v.w);
    }
    __syncthreads();
    int qg = t & 15;
    int ng = (t >> 4) * 4;
    unsigned long long acc[4][2];
#pragma unroll
    for (int i = 0; i < 4; i++) { acc[i][0] = 0ull; acc[i][1] = 0ull; }

    const float2* wrow = sWd + qg * 2;
#pragma unroll 8
    for (int k = 0; k < 64; k++) {
        unsigned long long w01 = *(const unsigned long long*)(wrow + k * 32);
        unsigned long long w23 = *(const unsigned long long*)(wrow + k * 32 + 1);
#pragma unroll
        for (int i = 0; i < 4; i++) {
            unsigned long long xx = *(const unsigned long long*)(sx2 + (ng + i) * 64 + k);
            asm("fma.rn.f32x2 %0, %1, %2, %0;" : "+l"(acc[i][0]) : "l"(xx), "l"(w01));
            asm("fma.rn.f32x2 %0, %1, %2, %0;" : "+l"(acc[i][1]) : "l"(xx), "l"(w23));
        }
    }
#pragma unroll
    for (int i = 0; i < 4; i++) {
        int n = nbase + ng + i;
        if (n >= NN) break;
        float dv = g_dinv[n];
        float lo0, hi0, lo1, hi1;
        asm("mov.b64 {%0,%1}, %2;" : "=f"(lo0), "=f"(hi0) : "l"(acc[i][0]));
        asm("mov.b64 {%0,%1}, %2;" : "=f"(lo1), "=f"(hi1) : "l"(acc[i][1]));
        __half2 h0 = __float22half2_rn(make_float2(lo0 * dv, hi0 * dv));
        __half2 h1 = __float22half2_rn(make_float2(lo1 * dv, hi1 * dv));
        uint2 packed = make_uint2(reinterpret_cast<unsigned&>(h0),
                                  reinterpret_cast<unsigned&>(h1));
        ((uint2*)g_hsh)[n * 16 + qg] = packed;
    }
}

// ---------------- gather + finalize (layers 1,2): lane-batched idx, 8-deep MLP ----------------
__global__ void __launch_bounds__(256) k_gather(
        const float* __restrict__ b, const float* __restrict__ gm,
        const float* __restrict__ be, const float* __restrict__ rm,
        const float* __restrict__ rv) {
    int lane = threadIdx.x & 31;
    int node = blockIdx.x * 8 + (threadIdx.x >> 5);
    if (node >= NN) return;

    int j = lane * 2;
    float scx = gm[j] * rsqrtf(rv[j] + BN_EPS);
    float scy = gm[j + 1] * rsqrtf(rv[j + 1] + BN_EPS);
    float shx = (b[j] - rm[j]) * scx + be[j];
    float shy = (b[j + 1] - rm[j + 1]) * scy + be[j + 1];

    const __half2* __restrict__ hs2 = g_hsh;
    float2 acc = __half22float2(hs2[node * 32 + lane]);   // self-loop term

    int beg = g_rowptr[node];
    int m = g_rowend[node] - beg;
    const int* __restrict__ idx = g_csrsrc + beg;

    for (int base = 0; base < m; base += 32) {
        int rem = m - base;
        int cnt = (rem < 32) ? rem : 32;
        int myidx = (lane < cnt) ? idx[base + lane] : 0;
        int k = 0;
        for (; k + 8 <= cnt; k += 8) {
            int s0 = __shfl_sync(0xffffffffu, myidx, k);
            int s1 = __shfl_sync(0xffffffffu, myidx, k + 1);
            int s2 = __shfl_sync(0xffffffffu, myidx, k + 2);
            int s3 = __shfl_sync(0xffffffffu, myidx, k + 3);
            int s4 = __shfl_sync(0xffffffffu, myidx, k + 4);
            int s5 = __shfl_sync(0xffffffffu, myidx, k + 5);
            int s6 = __shfl_sync(0xffffffffu, myidx, k + 6);
            int s7 = __shfl_sync(0xffffffffu, myidx, k + 7);
            float2 v0 = __half22float2(hs2[s0 * 32 + lane]);
            float2 v1 = __half22float2(hs2[s1 * 32 + lane]);
            float2 v2 = __half22float2(hs2[s2 * 32 + lane]);
            float2 v3 = __half22float2(hs2[s3 * 32 + lane]);
            float2 v4 = __half22float2(hs2[s4 * 32 + lane]);
            float2 v5 = __half22float2(hs2[s5 * 32 + lane]);
            float2 v6 = __half22float2(hs2[s6 * 32 + lane]);
            float2 v7 = __half22float2(hs2[s7 * 32 + lane]);
            acc.x += ((v0.x + v1.x) + (v2.x + v3.x)) + ((v4.x + v5.x) + (v6.x + v7.x));
            acc.y += ((v0.y + v1.y) + (v2.y + v3.y)) + ((v4.y + v5.y) + (v6.y + v7.y));
        }
        for (; k + 4 <= cnt; k += 4) {
            int s0 = __shfl_sync(0xffffffffu, myidx, k);
            int s1 = __shfl_sync(0xffffffffu, myidx, k + 1);
            int s2 = __shfl_sync(0xffffffffu, myidx, k + 2);
            int s3 = __shfl_sync(0xffffffffu, myidx, k + 3);
            float2 v0 = __half22float2(hs2[s0 * 32 + lane]);
            float2 v1 = __half22float2(hs2[s1 * 32 + lane]);
            float2 v2 = __half22float2(hs2[s2 * 32 + lane]);
            float2 v3 = __half22float2(hs2[s3 * 32 + lane]);
            acc.x += (v0.x + v1.x) + (v2.x + v3.x);
            acc.y += (v0.y + v1.y) + (v2.y + v3.y);
        }
        for (; k < cnt; k++) {
            int s = __shfl_sync(0xffffffffu, myidx, k);
            float2 v = __half22float2(hs2[s * 32 + lane]);
            acc.x += v.x; acc.y += v.y;
        }
    }

    float dv = g_dinv[node];
    float2 o;
    o.x = fmaxf(fmaf(acc.x * dv, scx, shx), 0.f);
    o.y = fmaxf(fmaf(acc.y * dv, scy, shy), 0.f);
    ((float2*)g_x)[node * 32 + lane] = o;
}

// ---------------- pooling: sorted batch_idx -> run-length reduction ----------------
#define POOL_NB 128
__global__ void k_pool(const int* __restrict__ bidx) {
    int j = threadIdx.x;                // 64 threads = dims
    int n0 = blockIdx.x * POOL_NB;
    if (n0 >= NN) return;
    int cur = bidx[n0];
    float s = 0.f, mx = 0.f, c = 0.f;
    for (int i = 0; i < POOL_NB; i++) {
        int n = n0 + i;
        if (n >= NN) break;
        int gidx = bidx[n];
        if (gidx != cur) {
            atomicAdd(&g_gsum[cur * 64 + j], s);
            atomicMax(&g_gmax[cur * 64 + j], __float_as_int(mx));
            if (j == 0) atomicAdd(&g_gcnt[cur], c);
            cur = gidx; s = 0.f; mx = 0.f; c = 0.f;
        }
        float v = g_x[n * 64 + j];
        s += v;
        mx = fmaxf(mx, v);
        c += 1.f;
    }
    atomicAdd(&g_gsum[cur * 64 + j], s);
    atomicMax(&g_gmax[cur * 64 + j], __float_as_int(mx));
    if (j == 0) atomicAdd(&g_gcnt[cur], c);
}

// ---------------- MLP head (+ cleanup of pooling accumulators) ----------------
__global__ void k_mlp(const float* __restrict__ mW1, const float* __restrict__ mb1,
                      const float* __restrict__ mW2, const float* __restrict__ mb2,
                      const float* __restrict__ mW3, const float* __restrict__ mb3,
                      float* __restrict__ out) {
    __shared__ float xg[128];
    __shared__ float h1[32];
    __shared__ float h2[16];
    int g = blockIdx.x;
    int t = threadIdx.x;                // 32 threads
    float cnt = fmaxf(g_gcnt[g], 1.f);
    for (int j = t; j < 64; j += 32) {
        xg[j]      = g_gsum[g * 64 + j] / cnt;
        xg[64 + j] = __int_as_float(g_gmax[g * 64 + j]);
    }
    __syncthreads();
    for (int j = t; j < 64; j += 32) {
        g_gsum[g * 64 + j] = 0.f;
        g_gmax[g * 64 + j] = 0;
    }
    if (t == 0) g_gcnt[g] = 0.f;
    {
        float acc = mb1[t];
        for (int k = 0; k < 128; k++) acc += xg[k] * mW1[k * 32 + t];
        h1[t] = fmaxf(acc, 0.f);
    }
    __syncthreads();
    if (t < 16) {
        float acc = mb2[t];
        for (int k = 0; k < 32; k++) acc += h1[k] * mW2[k * 16 + t];
        h2[t] = fmaxf(acc, 0.f);
    }
    __syncthreads();
    if (t == 0) {
        float acc = mb3[0];
        for (int k = 0; k < 16; k++) acc += h2[k] * mW3[k];
        out[g] = acc;
    }
}

extern "C" void kernel_launch(void* const* d_in, const int* in_sizes, int n_in,
                              void* d_out, int out_size) {
    const float* x    = (const float*)d_in[0];
    const int*   ei   = (const int*)  d_in[1];
    const int*   bidx = (const int*)  d_in[2];
    const float* W[3]  = {(const float*)d_in[3],  (const float*)d_in[9],  (const float*)d_in[15]};
    const float* b[3]  = {(const float*)d_in[4],  (const float*)d_in[10], (const float*)d_in[16]};
    const float* gm[3] = {(const float*)d_in[5],  (const float*)d_in[11], (const float*)d_in[17]};
    const float* be[3] = {(const float*)d_in[6],  (const float*)d_in[12], (const float*)d_in[18]};
    const float* rm[3] = {(const float*)d_in[7],  (const float*)d_in[13], (const float*)d_in[19]};
    const float* rv[3] = {(const float*)d_in[8],  (const float*)d_in[14], (const float*)d_in[20]};
    const float* mW1 = (const float*)d_in[21];
    const float* mb1 = (const float*)d_in[22];
    const float* mW2 = (const float*)d_in[23];
    const float* mb2 = (const float*)d_in[24];
    const float* mW3 = (const float*)d_in[25];
    const float* mb3 = (const float*)d_in[26];
    float* out = (float*)d_out;

    const int T = 256;
    int degBlocks  = (EE + T - 1) / T;
    int nBlocks    = (NN + T - 1) / T;
    int l0Blocks   = (NN + 63) / 64;
    int mmABlocks  = (NN + 63) / 64;
    int gatBlocks  = (NN + 7) / 8;
    int poolBlocks = (NN + POOL_NB - 1) / POOL_NB;

    k_deg<<<degBlocks, T>>>(ei);
    k_alloc<<<nBlocks, T>>>(x);
    k_csr<<<degBlocks, T>>>(ei);

    k_layer0<<<l0Blocks, 256>>>(W[0], b[0], gm[0], be[0], rm[0], rv[0]);

    for (int l = 1; l < 3; l++) {
        k_mmA<<<mmABlocks, T>>>(W[l]);
        k_gather<<<gatBlocks, T>>>(b[l], gm[l], be[l], rm[l], rv[l]);
    }

    k_pool<<<poolBlocks, 64>>>(bidx);
    k_mlp<<<GG, 32>>>(mW1, mb1, mW2, mb2, mW3, mb3, out);
}

// round 9
// speedup vs baseline: 1.0327x; 1.0327x over previous
#include <cuda_runtime.h>
#include <cuda_fp16.h>
#include <cuda_bf16.h>

#define NN 100000
#define EE 1600000
#define GG 256
#define HH 64
#define BN_EPS 1e-5f

// ---------------- scratch (device globals; zero-initialized at load) ----------------
__device__ int     g_deg[NN];          // re-zeroed by k_csr each run
__device__ int     g_total;            // re-zeroed by k_csr each run
__device__ float   g_dinv[NN];
__device__ float4  g_xs[NN];           // dinv * x (3-wide, w=0)
__device__ __half2 g_hsh[NN * 32];     // (x @ W) * dinv, fp16 (64 dims = 32 half2)
__device__ float   g_x[NN * HH];       // layer activations (fp32)
__device__ int     g_rowptr[NN];
__device__ int     g_rowend[NN];
__device__ int     g_cursor[NN];
__device__ int     g_csrsrc[EE];
__device__ float   g_gsum[GG * HH];    // re-zeroed by k_mlp each run
__device__ int     g_gmax[GG * HH];    // re-zeroed by k_mlp each run
__device__ float   g_gcnt[GG];         // re-zeroed by k_mlp each run

__device__ __forceinline__ unsigned pack_half2(float a, float b) {
    __half2 h = __float22half2_rn(make_float2(a, b));
    return reinterpret_cast<unsigned&>(h);
}

// ---------------- degree histogram (by dst) ----------------
__global__ void k_deg(const int* __restrict__ ei) {
    int e = blockIdx.x * blockDim.x + threadIdx.x;
    if (e < EE) atomicAdd(&g_deg[ei[EE + e]], 1);
}

// ---------------- CSR slot allocation: warp-aggregated atomic, no scan ----------------
__global__ void k_alloc(const float* __restrict__ x) {
    int i = blockIdx.x * blockDim.x + threadIdx.x;
    int lane = threadIdx.x & 31;
    int d = (i < NN) ? g_deg[i] : 0;
    int incl = d;
#pragma unroll
    for (int off = 1; off < 32; off <<= 1) {
        int v = __shfl_up_sync(0xffffffffu, incl, off);
        if (lane >= off) incl += v;
    }
    int total = __shfl_sync(0xffffffffu, incl, 31);
    int base = 0;
    if (lane == 31) base = atomicAdd(&g_total, total);
    base = __shfl_sync(0xffffffffu, base, 31);
    int excl = base + incl - d;
    if (i < NN) {
        g_rowptr[i] = excl;
        g_rowend[i] = excl + d;
        g_cursor[i] = excl;
        float dv = rsqrtf((float)d + 1.0f);
        g_dinv[i] = dv;
        g_xs[i] = make_float4(x[i * 3] * dv, x[i * 3 + 1] * dv, x[i * 3 + 2] * dv, 0.f);
    }
}

// ---------------- CSR fill (+ cleanup of deg/total for next replay) ----------------
__global__ void k_csr(const int* __restrict__ ei) {
    int e = blockIdx.x * blockDim.x + threadIdx.x;
    if (e < NN) g_deg[e] = 0;
    if (e == 0) g_total = 0;
    if (e < EE) {
        int s = ei[e];
        int d = ei[EE + e];
        int p = atomicAdd(&g_cursor[d], 1);
        g_csrsrc[p] = s;
    }
}

// ---------------- layer 0 fused: parallel input-space gather + GEMM + BN + ReLU ----------------
__global__ void __launch_bounds__(256) k_layer0(const float* __restrict__ W0,
        const float* __restrict__ b, const float* __restrict__ gm,
        const float* __restrict__ be, const float* __restrict__ rm,
        const float* __restrict__ rv) {
    __shared__ float sW[192];
    __shared__ float sxa[64][3];
    int t = threadIdx.x;
    int lane = t & 31;
    int warp = t >> 5;
    if (t < 192) sW[t] = W0[t];

    int nl = warp * 8 + (lane >> 2);   // 0..63 local node
    int sub = lane & 3;
    int n = blockIdx.x * 64 + nl;

    float ax = 0.f, ay = 0.f, az = 0.f;
    if (n < NN) {
        int beg = g_rowptr[n], end = g_rowend[n];
        const int* __restrict__ idx = g_csrsrc;
        for (int k = beg + sub; k < end; k += 4) {
            float4 a = g_xs[idx[k]];
            ax += a.x; ay += a.y; az += a.z;
        }
    }
    ax += __shfl_xor_sync(0xffffffffu, ax, 1);
    ay += __shfl_xor_sync(0xffffffffu, ay, 1);
    az += __shfl_xor_sync(0xffffffffu, az, 1);
    ax += __shfl_xor_sync(0xffffffffu, ax, 2);
    ay += __shfl_xor_sync(0xffffffffu, ay, 2);
    az += __shfl_xor_sync(0xffffffffu, az, 2);
    if (sub == 0 && n < NN) {
        float4 self = g_xs[n];
        float dv = g_dinv[n];
        sxa[nl][0] = (ax + self.x) * dv;
        sxa[nl][1] = (ay + self.y) * dv;
        sxa[nl][2] = (az + self.z) * dv;
    }
    __syncthreads();

    int q = t & 15;
    int j = q * 4;
    float4 sc, sh;
    sc.x = gm[j] * rsqrtf(rv[j] + BN_EPS);
    sc.y = gm[j + 1] * rsqrtf(rv[j + 1] + BN_EPS);
    sc.z = gm[j + 2] * rsqrtf(rv[j + 2] + BN_EPS);
    sc.w = gm[j + 3] * rsqrtf(rv[j + 3] + BN_EPS);
    sh.x = (b[j] - rm[j]) * sc.x + be[j];
    sh.y = (b[j + 1] - rm[j + 1]) * sc.y + be[j + 1];
    sh.z = (b[j + 2] - rm[j + 2]) * sc.z + be[j + 2];
    sh.w = (b[j + 3] - rm[j + 3]) * sc.w + be[j + 3];
    float w0x = sW[j],       w0y = sW[j + 1],       w0z = sW[j + 2],       w0w = sW[j + 3];
    float w1x = sW[64 + j],  w1y = sW[64 + j + 1],  w1z = sW[64 + j + 2],  w1w = sW[64 + j + 3];
    float w2x = sW[128 + j], w2y = sW[128 + j + 1], w2z = sW[128 + j + 2], w2w = sW[128 + j + 3];
#pragma unroll
    for (int r = 0; r < 4; r++) {
        int nl2 = r * 16 + (t >> 4);
        int gn = blockIdx.x * 64 + nl2;
        if (gn >= NN) break;
        float a0 = sxa[nl2][0], a1 = sxa[nl2][1], a2 = sxa[nl2][2];
        float4 o;
        o.x = fmaxf(fmaf(a0 * w0x + a1 * w1x + a2 * w2x, sc.x, sh.x), 0.f);
        o.y = fmaxf(fmaf(a0 * w0y + a1 * w1y + a2 * w2y, sc.y, sh.y), 0.f);
        o.z = fmaxf(fmaf(a0 * w0z + a1 * w1z + a2 * w2z, sc.z, sh.z), 0.f);
        o.w = fmaxf(fmaf(a0 * w0w + a1 * w1w + a2 * w2w, sc.w, sh.w), 0.f);
        ((float4*)g_x)[gn * 16 + q] = o;
    }
}

// ---------------- layers 1,2 GEMM: crossbar-minimal, broadcast-w, k-paired f32x2 ----------------
// Block = 32 nodes x 64 cols, 256 threads. lane = node, warp = 8 cols.
// acc[c] f32x2 accumulates (even-k, odd-k) partial sums; combined at the end.
__global__ void __launch_bounds__(256) k_mmA(const float* __restrict__ W) {
    __shared__ float  sxn[32 * 66];    // [node][k], row stride 66 (bank spread, 8B align)
    __shared__ float2 swk[64 * 34];    // [c][kp] = (W[2kp][c], W[2kp+1][c]), stride 34
    int t = threadIdx.x;
    int nbase = blockIdx.x * 32;

    // stage x: natural layout, coalesced float4 reads
#pragma unroll
    for (int i = t; i < 512; i += 256) {
        int n = i >> 4, q = i & 15;
        int gn = nbase + n;
        float4 v = (gn < NN) ? ((const float4*)g_x)[gn * 16 + q]
                             : make_float4(0.f, 0.f, 0.f, 0.f);
        float* dst = sxn + n * 66 + q * 4;
        *(float2*)dst = make_float2(v.x, v.y);
        *(float2*)(dst + 2) = make_float2(v.z, v.w);
    }
    // stage w as k-pairs: W[k][c] row-major; consecutive threads read consecutive c
#pragma unroll
    for (int i = t; i < 2048; i += 256) {
        int kp = i >> 6, c = i & 63;
        swk[c * 34 + kp] = make_float2(W[(2 * kp) * 64 + c], W[(2 * kp + 1) * 64 + c]);
    }
    __syncthreads();

    int lane = t & 31, warp = t >> 5;
    int c0 = warp * 8;
    int n = nbase + lane;
    const float* xr = sxn + lane * 66;
    unsigned long long acc[8];
#pragma unroll
    for (int c = 0; c < 8; c++) acc[c] = 0ull;

#pragma unroll 8
    for (int kp = 0; kp < 32; kp++) {
        unsigned long long xx = *(const unsigned long long*)(xr + 2 * kp);  // (x[2kp], x[2kp+1])
#pragma unroll
        for (int c = 0; c < 8; c++) {
            unsigned long long wv = *(const unsigned long long*)(swk + (c0 + c) * 34 + kp); // bcast
            asm("fma.rn.f32x2 %0, %1, %2, %0;" : "+l"(acc[c]) : "l"(xx), "l"(wv));
        }
    }

    if (n < NN) {
        float dv = g_dinv[n];
        float r[8];
#pragma unroll
        for (int c = 0; c < 8; c++) {
            float lo, hi;
            asm("mov.b64 {%0,%1}, %2;" : "=f"(lo), "=f"(hi) : "l"(acc[c]));
            r[c] = (lo + hi) * dv;
        }
        uint4 o;
        o.x = pack_half2(r[0], r[1]);
        o.y = pack_half2(r[2], r[3]);
        o.z = pack_half2(r[4], r[5]);
        o.w = pack_half2(r[6], r[7]);
        *(uint4*)((__half*)g_hsh + n * 64 + c0) = o;
    }
}

// ---------------- gather + finalize (layers 1,2): lane-batched idx + shfl (R7 form) ----------------
__global__ void __launch_bounds__(256) k_gather(
        const float* __restrict__ b, const float* __restrict__ gm,
        const float* __restrict__ be, const float* __restrict__ rm,
        const float* __restrict__ rv) {
    int lane = threadIdx.x & 31;
    int node = blockIdx.x * 8 + (threadIdx.x >> 5);
    if (node >= NN) return;

    int j = lane * 2;
    float scx = gm[j] * rsqrtf(rv[j] + BN_EPS);
    float scy = gm[j + 1] * rsqrtf(rv[j + 1] + BN_EPS);
    float shx = (b[j] - rm[j]) * scx + be[j];
    float shy = (b[j + 1] - rm[j + 1]) * scy + be[j + 1];

    const __half2* __restrict__ hs2 = g_hsh;
    float2 acc = __half22float2(hs2[node * 32 + lane]);   // self-loop term

    int beg = g_rowptr[node];
    int m = g_rowend[node] - beg;
    const int* __restrict__ idx = g_csrsrc + beg;

    for (int base = 0; base < m; base += 32) {
        int rem = m - base;
        int cnt = (rem < 32) ? rem : 32;
        int myidx = (lane < cnt) ? idx[base + lane] : 0;
        int k = 0;
        for (; k + 4 <= cnt; k += 4) {
            int s0 = __shfl_sync(0xffffffffu, myidx, k);
            int s1 = __shfl_sync(0xffffffffu, myidx, k + 1);
            int s2 = __shfl_sync(0xffffffffu, myidx, k + 2);
            int s3 = __shfl_sync(0xffffffffu, myidx, k + 3);
            float2 v0 = __half22float2(hs2[s0 * 32 + lane]);
            float2 v1 = __half22float2(hs2[s1 * 32 + lane]);
            float2 v2 = __half22float2(hs2[s2 * 32 + lane]);
            float2 v3 = __half22float2(hs2[s3 * 32 + lane]);
            acc.x += (v0.x + v1.x) + (v2.x + v3.x);
            acc.y += (v0.y + v1.y) + (v2.y + v3.y);
        }
        for (; k < cnt; k++) {
            int s = __shfl_sync(0xffffffffu, myidx, k);
            float2 v = __half22float2(hs2[s * 32 + lane]);
            acc.x += v.x; acc.y += v.y;
        }
    }

    float dv = g_dinv[node];
    float2 o;
    o.x = fmaxf(fmaf(acc.x * dv, scx, shx), 0.f);
    o.y = fmaxf(fmaf(acc.y * dv, scy, shy), 0.f);
    ((float2*)g_x)[node * 32 + lane] = o;
}

// ---------------- pooling: sorted batch_idx -> run-length reduction ----------------
#define POOL_NB 128
__global__ void k_pool(const int* __restrict__ bidx) {
    int j = threadIdx.x;                // 64 threads = dims
    int n0 = blockIdx.x * POOL_NB;
    if (n0 >= NN) return;
    int cur = bidx[n0];
    float s = 0.f, mx = 0.f, c = 0.f;
    for (int i = 0; i < POOL_NB; i++) {
        int n = n0 + i;
        if (n >= NN) break;
        int gidx = bidx[n];
        if (gidx != cur) {
            atomicAdd(&g_gsum[cur * 64 + j], s);
            atomicMax(&g_gmax[cur * 64 + j], __float_as_int(mx));
            if (j == 0) atomicAdd(&g_gcnt[cur], c);
            cur = gidx; s = 0.f; mx = 0.f; c = 0.f;
        }
        float v = g_x[n * 64 + j];
        s += v;
        mx = fmaxf(mx, v);
        c += 1.f;
    }
    atomicAdd(&g_gsum[cur * 64 + j], s);
    atomicMax(&g_gmax[cur * 64 + j], __float_as_int(mx));
    if (j == 0) atomicAdd(&g_gcnt[cur], c);
}

// ---------------- MLP head (+ cleanup of pooling accumulators) ----------------
__global__ void k_mlp(const float* __restrict__ mW1, const float* __restrict__ mb1,
                      const float* __restrict__ mW2, const float* __restrict__ mb2,
                      const float* __restrict__ mW3, const float* __restrict__ mb3,
                      float* __restrict__ out) {
    __shared__ float xg[128];
    __shared__ float h1[32];
    __shared__ float h2[16];
    int g = blockIdx.x;
    int t = threadIdx.x;                // 32 threads
    float cnt = fmaxf(g_gcnt[g], 1.f);
    for (int j = t; j < 64; j += 32) {
        xg[j]      = g_gsum[g * 64 + j] / cnt;
        xg[64 + j] = __int_as_float(g_gmax[g * 64 + j]);
    }
    __syncthreads();
    for (int j = t; j < 64; j += 32) {
        g_gsum[g * 64 + j] = 0.f;
        g_gmax[g * 64 + j] = 0;
    }
    if (t == 0) g_gcnt[g] = 0.f;
    {
        float acc = mb1[t];
        for (int k = 0; k < 128; k++) acc += xg[k] * mW1[k * 32 + t];
        h1[t] = fmaxf(acc, 0.f);
    }
    __syncthreads();
    if (t < 16) {
        float acc = mb2[t];
        for (int k = 0; k < 32; k++) acc += h1[k] * mW2[k * 16 + t];
        h2[t] = fmaxf(acc, 0.f);
    }
    __syncthreads();
    if (t == 0) {
        float acc = mb3[0];
        for (int k = 0; k < 16; k++) acc += h2[k] * mW3[k];
        out[g] = acc;
    }
}

extern "C" void kernel_launch(void* const* d_in, const int* in_sizes, int n_in,
                              void* d_out, int out_size) {
    const float* x    = (const float*)d_in[0];
    const int*   ei   = (const int*)  d_in[1];
    const int*   bidx = (const int*)  d_in[2];
    const float* W[3]  = {(const float*)d_in[3],  (const float*)d_in[9],  (const float*)d_in[15]};
    const float* b[3]  = {(const float*)d_in[4],  (const float*)d_in[10], (const float*)d_in[16]};
    const float* gm[3] = {(const float*)d_in[5],  (const float*)d_in[11], (const float*)d_in[17]};
    const float* be[3] = {(const float*)d_in[6],  (const float*)d_in[12], (const float*)d_in[18]};
    const float* rm[3] = {(const float*)d_in[7],  (const float*)d_in[13], (const float*)d_in[19]};
    const float* rv[3] = {(const float*)d_in[8],  (const float*)d_in[14], (const float*)d_in[20]};
    const float* mW1 = (const float*)d_in[21];
    const float* mb1 = (const float*)d_in[22];
    const float* mW2 = (const float*)d_in[23];
    const float* mb2 = (const float*)d_in[24];
    const float* mW3 = (const float*)d_in[25];
    const float* mb3 = (const float*)d_in[26];
    float* out = (float*)d_out;

    const int T = 256;
    int degBlocks  = (EE + T - 1) / T;
    int nBlocks    = (NN + T - 1) / T;
    int l0Blocks   = (NN + 63) / 64;
    int mmABlocks  = (NN + 31) / 32;
    int gatBlocks  = (NN + 7) / 8;
    int poolBlocks = (NN + POOL_NB - 1) / POOL_NB;

    k_deg<<<degBlocks, T>>>(ei);
    k_alloc<<<nBlocks, T>>>(x);
    k_csr<<<degBlocks, T>>>(ei);

    k_layer0<<<l0Blocks, 256>>>(W[0], b[0], gm[0], be[0], rm[0], rv[0]);

    for (int l = 1; l < 3; l++) {
        k_mmA<<<mmABlocks, T>>>(W[l]);
        k_gather<<<gatBlocks, T>>>(b[l], gm[l], be[l], rm[l], rv[l]);
    }

    k_pool<<<poolBlocks, 64>>>(bidx);
    k_mlp<<<GG, 32>>>(mW1, mb1, mW2, mb2, mW3, mb3, out);
}

// round 10
// speedup vs baseline: 1.1752x; 1.1379x over previous
#include <cuda_runtime.h>
#include <cuda_fp16.h>
#include <cuda_bf16.h>

#define NN 100000
#define EE 1600000
#define GG 256
#define HH 64
#define BN_EPS 1e-5f

// ---------------- scratch (device globals; zero-initialized at load) ----------------
__device__ int     g_deg[NN];          // re-zeroed by k_csr each run
__device__ int     g_total;            // re-zeroed by k_csr each run
__device__ float   g_dinv[NN];
__device__ float4  g_xs[NN];           // dinv * x (3-wide, w=0)
__device__ __half2 g_hsh[NN * 32];     // (x @ W) * dinv, fp16 (64 dims = 32 half2)
__device__ float   g_x[NN * HH];       // layer activations (fp32)
__device__ int     g_rowptr[NN];
__device__ int     g_rowend[NN];
__device__ int     g_cursor[NN];
__device__ int     g_csrsrc[EE];
__device__ float   g_gsum[GG * HH];    // re-zeroed by k_mlp each run
__device__ int     g_gmax[GG * HH];    // re-zeroed by k_mlp each run
__device__ float   g_gcnt[GG];         // re-zeroed by k_mlp each run

__device__ __forceinline__ unsigned pack_half2(float a, float b) {
    __half2 h = __float22half2_rn(make_float2(a, b));
    return reinterpret_cast<unsigned&>(h);
}

// ---------------- degree histogram (by dst), 4 edges/thread ----------------
__global__ void k_deg(const int* __restrict__ ei) {
    int i = blockIdx.x * blockDim.x + threadIdx.x;
    if (i < EE / 4) {
        int4 d = ((const int4*)(ei + EE))[i];
        atomicAdd(&g_deg[d.x], 1);
        atomicAdd(&g_deg[d.y], 1);
        atomicAdd(&g_deg[d.z], 1);
        atomicAdd(&g_deg[d.w], 1);
    }
}

// ---------------- CSR slot allocation: warp-aggregated atomic, no scan ----------------
__global__ void k_alloc(const float* __restrict__ x) {
    int i = blockIdx.x * blockDim.x + threadIdx.x;
    int lane = threadIdx.x & 31;
    int d = (i < NN) ? g_deg[i] : 0;
    int incl = d;
#pragma unroll
    for (int off = 1; off < 32; off <<= 1) {
        int v = __shfl_up_sync(0xffffffffu, incl, off);
        if (lane >= off) incl += v;
    }
    int total = __shfl_sync(0xffffffffu, incl, 31);
    int base = 0;
    if (lane == 31) base = atomicAdd(&g_total, total);
    base = __shfl_sync(0xffffffffu, base, 31);
    int excl = base + incl - d;
    if (i < NN) {
        g_rowptr[i] = excl;
        g_rowend[i] = excl + d;
        g_cursor[i] = excl;
        float dv = rsqrtf((float)d + 1.0f);
        g_dinv[i] = dv;
        g_xs[i] = make_float4(x[i * 3] * dv, x[i * 3 + 1] * dv, x[i * 3 + 2] * dv, 0.f);
    }
}

// ---------------- CSR fill, 4 edges/thread (+ cleanup of deg/total) ----------------
__global__ void k_csr(const int* __restrict__ ei) {
    int i = blockIdx.x * blockDim.x + threadIdx.x;
    if (i < NN / 4) ((int4*)g_deg)[i] = make_int4(0, 0, 0, 0);
    if (i == 0) g_total = 0;
    if (i < EE / 4) {
        int4 s = ((const int4*)ei)[i];
        int4 d = ((const int4*)(ei + EE))[i];
        g_csrsrc[atomicAdd(&g_cursor[d.x], 1)] = s.x;
        g_csrsrc[atomicAdd(&g_cursor[d.y], 1)] = s.y;
        g_csrsrc[atomicAdd(&g_cursor[d.z], 1)] = s.z;
        g_csrsrc[atomicAdd(&g_cursor[d.w], 1)] = s.w;
    }
}

// ---------------- layer 0 fused: parallel input-space gather + GEMM + BN + ReLU ----------------
__global__ void __launch_bounds__(256) k_layer0(const float* __restrict__ W0,
        const float* __restrict__ b, const float* __restrict__ gm,
        const float* __restrict__ be, const float* __restrict__ rm,
        const float* __restrict__ rv) {
    __shared__ float sW[192];
    __shared__ float sxa[64][3];
    int t = threadIdx.x;
    int lane = t & 31;
    int warp = t >> 5;
    if (t < 192) sW[t] = W0[t];

    int nl = warp * 8 + (lane >> 2);
    int sub = lane & 3;
    int n = blockIdx.x * 64 + nl;

    float ax = 0.f, ay = 0.f, az = 0.f;
    if (n < NN) {
        int beg = g_rowptr[n], end = g_rowend[n];
        const int* __restrict__ idx = g_csrsrc;
        for (int k = beg + sub; k < end; k += 4) {
            float4 a = g_xs[idx[k]];
            ax += a.x; ay += a.y; az += a.z;
        }
    }
    ax += __shfl_xor_sync(0xffffffffu, ax, 1);
    ay += __shfl_xor_sync(0xffffffffu, ay, 1);
    az += __shfl_xor_sync(0xffffffffu, az, 1);
    ax += __shfl_xor_sync(0xffffffffu, ax, 2);
    ay += __shfl_xor_sync(0xffffffffu, ay, 2);
    az += __shfl_xor_sync(0xffffffffu, az, 2);
    if (sub == 0 && n < NN) {
        float4 self = g_xs[n];
        float dv = g_dinv[n];
        sxa[nl][0] = (ax + self.x) * dv;
        sxa[nl][1] = (ay + self.y) * dv;
        sxa[nl][2] = (az + self.z) * dv;
    }
    __syncthreads();

    int q = t & 15;
    int j = q * 4;
    float4 sc, sh;
    sc.x = gm[j] * rsqrtf(rv[j] + BN_EPS);
    sc.y = gm[j + 1] * rsqrtf(rv[j + 1] + BN_EPS);
    sc.z = gm[j + 2] * rsqrtf(rv[j + 2] + BN_EPS);
    sc.w = gm[j + 3] * rsqrtf(rv[j + 3] + BN_EPS);
    sh.x = (b[j] - rm[j]) * sc.x + be[j];
    sh.y = (b[j + 1] - rm[j + 1]) * sc.y + be[j + 1];
    sh.z = (b[j + 2] - rm[j + 2]) * sc.z + be[j + 2];
    sh.w = (b[j + 3] - rm[j + 3]) * sc.w + be[j + 3];
    float w0x = sW[j],       w0y = sW[j + 1],       w0z = sW[j + 2],       w0w = sW[j + 3];
    float w1x = sW[64 + j],  w1y = sW[64 + j + 1],  w1z = sW[64 + j + 2],  w1w = sW[64 + j + 3];
    float w2x = sW[128 + j], w2y = sW[128 + j + 1], w2z = sW[128 + j + 2], w2w = sW[128 + j + 3];
#pragma unroll
    for (int r = 0; r < 4; r++) {
        int nl2 = r * 16 + (t >> 4);
        int gn = blockIdx.x * 64 + nl2;
        if (gn >= NN) break;
        float a0 = sxa[nl2][0], a1 = sxa[nl2][1], a2 = sxa[nl2][2];
        float4 o;
        o.x = fmaxf(fmaf(a0 * w0x + a1 * w1x + a2 * w2x, sc.x, sh.x), 0.f);
        o.y = fmaxf(fmaf(a0 * w0y + a1 * w1y + a2 * w2y, sc.y, sh.y), 0.f);
        o.z = fmaxf(fmaf(a0 * w0z + a1 * w1z + a2 * w2z, sc.z, sh.z), 0.f);
        o.w = fmaxf(fmaf(a0 * w0w + a1 * w1w + a2 * w2w, sc.w, sh.w), 0.f);
        ((float4*)g_x)[gn * 16 + q] = o;
    }
}

// ---------------- layers 1,2 GEMM: crossbar-minimal, broadcast-w, k-paired f32x2 ----------------
__global__ void __launch_bounds__(256) k_mmA(const float* __restrict__ W) {
    __shared__ float  sxn[32 * 66];
    __shared__ float2 swk[64 * 34];
    int t = threadIdx.x;
    int nbase = blockIdx.x * 32;

#pragma unroll
    for (int i = t; i < 512; i += 256) {
        int n = i >> 4, q = i & 15;
        int gn = nbase + n;
        float4 v = (gn < NN) ? ((const float4*)g_x)[gn * 16 + q]
                             : make_float4(0.f, 0.f, 0.f, 0.f);
        float* dst = sxn + n * 66 + q * 4;
        *(float2*)dst = make_float2(v.x, v.y);
        *(float2*)(dst + 2) = make_float2(v.z, v.w);
    }
#pragma unroll
    for (int i = t; i < 2048; i += 256) {
        int kp = i >> 6, c = i & 63;
        swk[c * 34 + kp] = make_float2(W[(2 * kp) * 64 + c], W[(2 * kp + 1) * 64 + c]);
    }
    __syncthreads();

    int lane = t & 31, warp = t >> 5;
    int c0 = warp * 8;
    int n = nbase + lane;
    const float* xr = sxn + lane * 66;
    unsigned long long acc[8];
#pragma unroll
    for (int c = 0; c < 8; c++) acc[c] = 0ull;

#pragma unroll 8
    for (int kp = 0; kp < 32; kp++) {
        unsigned long long xx = *(const unsigned long long*)(xr + 2 * kp);
#pragma unroll
        for (int c = 0; c < 8; c++) {
            unsigned long long wv = *(const unsigned long long*)(swk + (c0 + c) * 34 + kp);
            asm("fma.rn.f32x2 %0, %1, %2, %0;" : "+l"(acc[c]) : "l"(xx), "l"(wv));
        }
    }

    if (n < NN) {
        float dv = g_dinv[n];
        float r[8];
#pragma unroll
        for (int c = 0; c < 8; c++) {
            float lo, hi;
            asm("mov.b64 {%0,%1}, %2;" : "=f"(lo), "=f"(hi) : "l"(acc[c]));
            r[c] = (lo + hi) * dv;
        }
        uint4 o;
        o.x = pack_half2(r[0], r[1]);
        o.y = pack_half2(r[2], r[3]);
        o.z = pack_half2(r[4], r[5]);
        o.w = pack_half2(r[6], r[7]);
        *(uint4*)((__half*)g_hsh + n * 64 + c0) = o;
    }
}

// ---------------- gather + finalize, layer 1: writes g_x ----------------
__global__ void __launch_bounds__(256) k_gather(
        const float* __restrict__ b, const float* __restrict__ gm,
        const float* __restrict__ be, const float* __restrict__ rm,
        const float* __restrict__ rv) {
    int lane = threadIdx.x & 31;
    int node = blockIdx.x * 8 + (threadIdx.x >> 5);
    if (node >= NN) return;

    int j = lane * 2;
    float scx = gm[j] * rsqrtf(rv[j] + BN_EPS);
    float scy = gm[j + 1] * rsqrtf(rv[j + 1] + BN_EPS);
    float shx = (b[j] - rm[j]) * scx + be[j];
    float shy = (b[j + 1] - rm[j + 1]) * scy + be[j + 1];

    const __half2* __restrict__ hs2 = g_hsh;
    float2 acc = __half22float2(hs2[node * 32 + lane]);

    int beg = g_rowptr[node];
    int m = g_rowend[node] - beg;
    const int* __restrict__ idx = g_csrsrc + beg;

    for (int base = 0; base < m; base += 32) {
        int rem = m - base;
        int cnt = (rem < 32) ? rem : 32;
        int myidx = (lane < cnt) ? idx[base + lane] : 0;
        int k = 0;
        for (; k + 4 <= cnt; k += 4) {
            int s0 = __shfl_sync(0xffffffffu, myidx, k);
            int s1 = __shfl_sync(0xffffffffu, myidx, k + 1);
            int s2 = __shfl_sync(0xffffffffu, myidx, k + 2);
            int s3 = __shfl_sync(0xffffffffu, myidx, k + 3);
            float2 v0 = __half22float2(hs2[s0 * 32 + lane]);
            float2 v1 = __half22float2(hs2[s1 * 32 + lane]);
            float2 v2 = __half22float2(hs2[s2 * 32 + lane]);
            float2 v3 = __half22float2(hs2[s3 * 32 + lane]);
            acc.x += (v0.x + v1.x) + (v2.x + v3.x);
            acc.y += (v0.y + v1.y) + (v2.y + v3.y);
        }
        for (; k < cnt; k++) {
            int s = __shfl_sync(0xffffffffu, myidx, k);
            float2 v = __half22float2(hs2[s * 32 + lane]);
            acc.x += v.x; acc.y += v.y;
        }
    }

    float dv = g_dinv[node];
    float2 o;
    o.x = fmaxf(fmaf(acc.x * dv, scx, shx), 0.f);
    o.y = fmaxf(fmaf(acc.y * dv, scy, shy), 0.f);
    ((float2*)g_x)[node * 32 + lane] = o;
}

// ---------------- gather layer 2 + FUSED POOLING (no g_x write, no k_pool) ----------------
// NN % 8 == 0 so every block has 8 valid nodes; batch_idx sorted -> few distinct
// graphs per block; stage rows in smem, leaders flush per distinct gid.
__global__ void __launch_bounds__(256) k_gather2(
        const int* __restrict__ bidx,
        const float* __restrict__ b, const float* __restrict__ gm,
        const float* __restrict__ be, const float* __restrict__ rm,
        const float* __restrict__ rv) {
    __shared__ float sval[8][64];
    __shared__ int   sgid[8];
    int lane = threadIdx.x & 31;
    int w = threadIdx.x >> 5;
    int node = blockIdx.x * 8 + w;

    int j = lane * 2;
    float scx = gm[j] * rsqrtf(rv[j] + BN_EPS);
    float scy = gm[j + 1] * rsqrtf(rv[j + 1] + BN_EPS);
    float shx = (b[j] - rm[j]) * scx + be[j];
    float shy = (b[j + 1] - rm[j + 1]) * scy + be[j + 1];

    const __half2* __restrict__ hs2 = g_hsh;
    float2 acc = __half22float2(hs2[node * 32 + lane]);

    int beg = g_rowptr[node];
    int m = g_rowend[node] - beg;
    const int* __restrict__ idx = g_csrsrc + beg;

    for (int base = 0; base < m; base += 32) {
        int rem = m - base;
        int cnt = (rem < 32) ? rem : 32;
        int myidx = (lane < cnt) ? idx[base + lane] : 0;
        int k = 0;
        for (; k + 4 <= cnt; k += 4) {
            int s0 = __shfl_sync(0xffffffffu, myidx, k);
            int s1 = __shfl_sync(0xffffffffu, myidx, k + 1);
            int s2 = __shfl_sync(0xffffffffu, myidx, k + 2);
            int s3 = __shfl_sync(0xffffffffu, myidx, k + 3);
            float2 v0 = __half22float2(hs2[s0 * 32 + lane]);
            float2 v1 = __half22float2(hs2[s1 * 32 + lane]);
            float2 v2 = __half22float2(hs2[s2 * 32 + lane]);
            float2 v3 = __half22float2(hs2[s3 * 32 + lane]);
            acc.x += (v0.x + v1.x) + (v2.x + v3.x);
            acc.y += (v0.y + v1.y) + (v2.y + v3.y);
        }
        for (; k < cnt; k++) {
            int s = __shfl_sync(0xffffffffu, myidx, k);
            float2 v = __half22float2(hs2[s * 32 + lane]);
            acc.x += v.x; acc.y += v.y;
        }
    }

    float dv = g_dinv[node];
    sval[w][j]     = fmaxf(fmaf(acc.x * dv, scx, shx), 0.f);
    sval[w][j + 1] = fmaxf(fmaf(acc.y * dv, scy, shy), 0.f);
    if (lane == 0) sgid[w] = bidx[node];
    __syncthreads();

    // flush: one leader warp per distinct gid in the block
    int gid = sgid[w];
    bool leader = (w == 0) || (sgid[w - 1] != gid);
    if (leader) {
        float sx = 0.f, sy = 0.f, mxx = 0.f, mxy = 0.f;
        int c = 0;
        for (int s2 = w; s2 < 8 && sgid[s2] == gid; s2++) {
            float vx = sval[s2][j], vy = sval[s2][j + 1];
            sx += vx; sy += vy;
            mxx = fmaxf(mxx, vx); mxy = fmaxf(mxy, vy);
            c++;
        }
        atomicAdd(&g_gsum[gid * 64 + j], sx);
        atomicAdd(&g_gsum[gid * 64 + j + 1], sy);
        atomicMax(&g_gmax[gid * 64 + j], __float_as_int(mxx));
        atomicMax(&g_gmax[gid * 64 + j + 1], __float_as_int(mxy));
        if (lane == 0) atomicAdd(&g_gcnt[gid], (float)c);
    }
}

// ---------------- MLP head (+ cleanup of pooling accumulators) ----------------
__global__ void k_mlp(const float* __restrict__ mW1, const float* __restrict__ mb1,
                      const float* __restrict__ mW2, const float* __restrict__ mb2,
                      const float* __restrict__ mW3, const float* __restrict__ mb3,
                      float* __restrict__ out) {
    __shared__ float xg[128];
    __shared__ float h1[32];
    __shared__ float h2[16];
    int g = blockIdx.x;
    int t = threadIdx.x;                // 32 threads
    float cnt = fmaxf(g_gcnt[g], 1.f);
    for (int j = t; j < 64; j += 32) {
        xg[j]      = g_gsum[g * 64 + j] / cnt;
        xg[64 + j] = __int_as_float(g_gmax[g * 64 + j]);
    }
    __syncthreads();
    for (int j = t; j < 64; j += 32) {
        g_gsum[g * 64 + j] = 0.f;
        g_gmax[g * 64 + j] = 0;
    }
    if (t == 0) g_gcnt[g] = 0.f;
    {
        float acc = mb1[t];
        for (int k = 0; k < 128; k++) acc += xg[k] * mW1[k * 32 + t];
        h1[t] = fmaxf(acc, 0.f);
    }
    __syncthreads();
    if (t < 16) {
        float acc = mb2[t];
        for (int k = 0; k < 32; k++) acc += h1[k] * mW2[k * 16 + t];
        h2[t] = fmaxf(acc, 0.f);
    }
    __syncthreads();
    if (t == 0) {
        float acc = mb3[0];
        for (int k = 0; k < 16; k++) acc += h2[k] * mW3[k];
        out[g] = acc;
    }
}

extern "C" void kernel_launch(void* const* d_in, const int* in_sizes, int n_in,
                              void* d_out, int out_size) {
    const float* x    = (const float*)d_in[0];
    const int*   ei   = (const int*)  d_in[1];
    const int*   bidx = (const int*)  d_in[2];
    const float* W[3]  = {(const float*)d_in[3],  (const float*)d_in[9],  (const float*)d_in[15]};
    const float* b[3]  = {(const float*)d_in[4],  (const float*)d_in[10], (const float*)d_in[16]};
    const float* gm[3] = {(const float*)d_in[5],  (const float*)d_in[11], (const float*)d_in[17]};
    const float* be[3] = {(const float*)d_in[6],  (const float*)d_in[12], (const float*)d_in[18]};
    const float* rm[3] = {(const float*)d_in[7],  (const float*)d_in[13], (const float*)d_in[19]};
    const float* rv[3] = {(const float*)d_in[8],  (const float*)d_in[14], (const float*)d_in[20]};
    const float* mW1 = (const float*)d_in[21];
    const float* mb1 = (const float*)d_in[22];
    const float* mW2 = (const float*)d_in[23];
    const float* mb2 = (const float*)d_in[24];
    const float* mW3 = (const float*)d_in[25];
    const float* mb3 = (const float*)d_in[26];
    float* out = (float*)d_out;

    const int T = 256;
    int deg4Blocks = (EE / 4 + T - 1) / T;
    int nBlocks    = (NN + T - 1) / T;
    int l0Blocks   = (NN + 63) / 64;
    int mmABlocks  = (NN + 31) / 32;
    int gatBlocks  = (NN + 7) / 8;      // NN % 8 == 0

    k_deg<<<deg4Blocks, T>>>(ei);
    k_alloc<<<nBlocks, T>>>(x);
    k_csr<<<deg4Blocks, T>>>(ei);

    k_layer0<<<l0Blocks, 256>>>(W[0], b[0], gm[0], be[0], rm[0], rv[0]);

    k_mmA<<<mmABlocks, T>>>(W[1]);
    k_gather<<<gatBlocks, T>>>(b[1], gm[1], be[1], rm[1], rv[1]);

    k_mmA<<<mmABlocks, T>>>(W[2]);
    k_gather2<<<gatBlocks, T>>>(bidx, b[2], gm[2], be[2], rm[2], rv[2]);

    k_mlp<<<GG, 32>>>(mW1, mb1, mW2, mb2, mW3, mb3, out);
}

// round 11
// speedup vs baseline: 1.1853x; 1.0086x over previous
#include <cuda_runtime.h>
#include <cuda_fp16.h>
#include <cuda_bf16.h>

#define NN 100000
#define EE 1600000
#define GG 256
#define HH 64
#define BN_EPS 1e-5f

// ---------------- scratch (device globals; zero-initialized at load) ----------------
__device__ int     g_deg[NN];          // re-zeroed by k_csr each run
__device__ int     g_total;            // re-zeroed by k_csr each run
__device__ float   g_dinv[NN];
__device__ float4  g_xs[NN];           // dinv * x (3-wide, w=0)
__device__ __half2 g_hsh[NN * 32];     // layer-1 hs (fp16)
__device__ __half2 g_hsh2[NN * 32];    // layer-2 hs (fp16)
__device__ int     g_rowptr[NN];
__device__ int     g_rowend[NN];
__device__ int     g_cursor[NN];
__device__ int     g_csrsrc[EE];
__device__ float   g_gsum[GG * HH];    // re-zeroed by k_mlp each run
__device__ int     g_gmax[GG * HH];    // re-zeroed by k_mlp each run
__device__ float   g_gcnt[GG];         // re-zeroed by k_mlp each run

__device__ __forceinline__ unsigned pack_half2(float a, float b) {
    __half2 h = __float22half2_rn(make_float2(a, b));
    return reinterpret_cast<unsigned&>(h);
}

// ---------------- degree histogram (by dst), 4 edges/thread ----------------
__global__ void k_deg(const int* __restrict__ ei) {
    int i = blockIdx.x * blockDim.x + threadIdx.x;
    if (i < EE / 4) {
        int4 d = ((const int4*)(ei + EE))[i];
        atomicAdd(&g_deg[d.x], 1);
        atomicAdd(&g_deg[d.y], 1);
        atomicAdd(&g_deg[d.z], 1);
        atomicAdd(&g_deg[d.w], 1);
    }
}

// ---------------- CSR slot allocation: warp-aggregated atomic, no scan ----------------
__global__ void k_alloc(const float* __restrict__ x) {
    int i = blockIdx.x * blockDim.x + threadIdx.x;
    int lane = threadIdx.x & 31;
    int d = (i < NN) ? g_deg[i] : 0;
    int incl = d;
#pragma unroll
    for (int off = 1; off < 32; off <<= 1) {
        int v = __shfl_up_sync(0xffffffffu, incl, off);
        if (lane >= off) incl += v;
    }
    int total = __shfl_sync(0xffffffffu, incl, 31);
    int base = 0;
    if (lane == 31) base = atomicAdd(&g_total, total);
    base = __shfl_sync(0xffffffffu, base, 31);
    int excl = base + incl - d;
    if (i < NN) {
        g_rowptr[i] = excl;
        g_rowend[i] = excl + d;
        g_cursor[i] = excl;
        float dv = rsqrtf((float)d + 1.0f);
        g_dinv[i] = dv;
        g_xs[i] = make_float4(x[i * 3] * dv, x[i * 3 + 1] * dv, x[i * 3 + 2] * dv, 0.f);
    }
}

// ---------------- CSR fill, 4 edges/thread (+ cleanup of deg/total) ----------------
__global__ void k_csr(const int* __restrict__ ei) {
    int i = blockIdx.x * blockDim.x + threadIdx.x;
    if (i < NN / 4) ((int4*)g_deg)[i] = make_int4(0, 0, 0, 0);
    if (i == 0) g_total = 0;
    if (i < EE / 4) {
        int4 s = ((const int4*)ei)[i];
        int4 d = ((const int4*)(ei + EE))[i];
        g_csrsrc[atomicAdd(&g_cursor[d.x], 1)] = s.x;
        g_csrsrc[atomicAdd(&g_cursor[d.y], 1)] = s.y;
        g_csrsrc[atomicAdd(&g_cursor[d.z], 1)] = s.z;
        g_csrsrc[atomicAdd(&g_cursor[d.w], 1)] = s.w;
    }
}

// ============ FUSED layer0 + GEMM1: gather3 -> GEMM0+BN+ReLU -> GEMM1 -> hsh1 ============
// Block = 32 nodes (NN % 32 == 0), 256 threads.
__global__ void __launch_bounds__(256) k_l0mm1(
        const float* __restrict__ W0,
        const float* __restrict__ b, const float* __restrict__ gm,
        const float* __restrict__ be, const float* __restrict__ rm,
        const float* __restrict__ rv,
        const float* __restrict__ W1) {
    __shared__ float  sxn[32 * 66];    // x rows (post BN/ReLU), stride 66
    __shared__ float2 swk[64 * 34];    // W1 k-pairs: [c][kp]
    __shared__ float  sW0[192];
    int t = threadIdx.x;
    int lane = t & 31, warp = t >> 5;
    int nbase = blockIdx.x * 32;

    if (t < 192) sW0[t] = W0[t];
#pragma unroll
    for (int i = t; i < 2048; i += 256) {
        int kp = i >> 6, c = i & 63;
        swk[c * 34 + kp] = make_float2(W1[(2 * kp) * 64 + c], W1[(2 * kp + 1) * 64 + c]);
    }

    // per-lane BN constants for 2 cols j, j+1
    int j = lane * 2;
    float scx = gm[j] * rsqrtf(rv[j] + BN_EPS);
    float scy = gm[j + 1] * rsqrtf(rv[j + 1] + BN_EPS);
    float shx = (b[j] - rm[j]) * scx + be[j];
    float shy = (b[j + 1] - rm[j + 1]) * scy + be[j + 1];
    float w0x = sW0[j],       w0y = sW0[j + 1];
    float w1x = sW0[64 + j],  w1y = sW0[64 + j + 1];
    float w2x = sW0[128 + j], w2y = sW0[128 + j + 1];
    // NOTE: sW0 read before a sync — but it was written by threads < 192 of this
    // block; we must sync after staging. Do the W-reads after __syncthreads.
    __syncthreads();
    w0x = sW0[j];       w0y = sW0[j + 1];
    w1x = sW0[64 + j];  w1y = sW0[64 + j + 1];
    w2x = sW0[128 + j]; w2y = sW0[128 + j + 1];

    // phase 1: each warp gathers+computes 4 nodes
#pragma unroll
    for (int i = 0; i < 4; i++) {
        int nl = warp * 4 + i;
        int node = nbase + nl;
        int beg = g_rowptr[node];
        int m = g_rowend[node] - beg;
        const int* __restrict__ idx = g_csrsrc + beg;
        float ax = 0.f, ay = 0.f, az = 0.f;
        for (int k = lane; k < m; k += 32) {
            float4 a = g_xs[idx[k]];
            ax += a.x; ay += a.y; az += a.z;
        }
#pragma unroll
        for (int off = 16; off > 0; off >>= 1) {
            ax += __shfl_xor_sync(0xffffffffu, ax, off);
            ay += __shfl_xor_sync(0xffffffffu, ay, off);
            az += __shfl_xor_sync(0xffffffffu, az, off);
        }
        float4 self = g_xs[node];
        float dv = g_dinv[node];
        float a0 = (ax + self.x) * dv;
        float a1 = (ay + self.y) * dv;
        float a2 = (az + self.z) * dv;
        float ox = fmaxf(fmaf(a0 * w0x + a1 * w1x + a2 * w2x, scx, shx), 0.f);
        float oy = fmaxf(fmaf(a0 * w0y + a1 * w1y + a2 * w2y, scy, shy), 0.f);
        *(float2*)(sxn + nl * 66 + j) = make_float2(ox, oy);
    }
    __syncthreads();

    // phase 2: GEMM1 (crossbar-minimal), lane = node, warp = 8 cols
    int c0 = warp * 8;
    int n = nbase + lane;
    const float* xr = sxn + lane * 66;
    unsigned long long acc[8];
#pragma unroll
    for (int c = 0; c < 8; c++) acc[c] = 0ull;
#pragma unroll 8
    for (int kp = 0; kp < 32; kp++) {
        unsigned long long xx = *(const unsigned long long*)(xr + 2 * kp);
#pragma unroll
        for (int c = 0; c < 8; c++) {
            unsigned long long wv = *(const unsigned long long*)(swk + (c0 + c) * 34 + kp);
            asm("fma.rn.f32x2 %0, %1, %2, %0;" : "+l"(acc[c]) : "l"(xx), "l"(wv));
        }
    }
    {
        float dv = g_dinv[n];
        float r[8];
#pragma unroll
        for (int c = 0; c < 8; c++) {
            float lo, hi;
            asm("mov.b64 {%0,%1}, %2;" : "=f"(lo), "=f"(hi) : "l"(acc[c]));
            r[c] = (lo + hi) * dv;
        }
        uint4 o;
        o.x = pack_half2(r[0], r[1]);
        o.y = pack_half2(r[2], r[3]);
        o.z = pack_half2(r[4], r[5]);
        o.w = pack_half2(r[6], r[7]);
        *(uint4*)((__half*)g_hsh + n * 64 + c0) = o;
    }
}

// ============ FUSED gather(l1) + GEMM2: gather hsh1 -> BN+ReLU -> GEMM2 -> hsh2 ============
// Block = 32 nodes, 256 threads. Phase 1: warp per node (4 sequential).
__global__ void __launch_bounds__(256) k_g1mm2(
        const float* __restrict__ b, const float* __restrict__ gm,
        const float* __restrict__ be, const float* __restrict__ rm,
        const float* __restrict__ rv,
        const float* __restrict__ W2) {
    __shared__ float  sxn[32 * 66];
    __shared__ float2 swk[64 * 34];
    int t = threadIdx.x;
    int lane = t & 31, warp = t >> 5;
    int nbase = blockIdx.x * 32;

#pragma unroll
    for (int i = t; i < 2048; i += 256) {
        int kp = i >> 6, c = i & 63;
        swk[c * 34 + kp] = make_float2(W2[(2 * kp) * 64 + c], W2[(2 * kp + 1) * 64 + c]);
    }

    int j = lane * 2;
    float scx = gm[j] * rsqrtf(rv[j] + BN_EPS);
    float scy = gm[j + 1] * rsqrtf(rv[j + 1] + BN_EPS);
    float shx = (b[j] - rm[j]) * scx + be[j];
    float shy = (b[j + 1] - rm[j + 1]) * scy + be[j + 1];

    const __half2* __restrict__ hs2 = g_hsh;

    // phase 1: each warp gathers 4 nodes (lane owns cols j, j+1)
#pragma unroll
    for (int i = 0; i < 4; i++) {
        int nl = warp * 4 + i;
        int node = nbase + nl;
        float2 acc = __half22float2(hs2[node * 32 + lane]);   // self-loop term
        int beg = g_rowptr[node];
        int m = g_rowend[node] - beg;
        const int* __restrict__ idx = g_csrsrc + beg;
        for (int base = 0; base < m; base += 32) {
            int rem = m - base;
            int cnt = (rem < 32) ? rem : 32;
            int myidx = (lane < cnt) ? idx[base + lane] : 0;
            int k = 0;
            for (; k + 4 <= cnt; k += 4) {
                int s0 = __shfl_sync(0xffffffffu, myidx, k);
                int s1 = __shfl_sync(0xffffffffu, myidx, k + 1);
                int s2 = __shfl_sync(0xffffffffu, myidx, k + 2);
                int s3 = __shfl_sync(0xffffffffu, myidx, k + 3);
                float2 v0 = __half22float2(hs2[s0 * 32 + lane]);
                float2 v1 = __half22float2(hs2[s1 * 32 + lane]);
                float2 v2 = __half22float2(hs2[s2 * 32 + lane]);
                float2 v3 = __half22float2(hs2[s3 * 32 + lane]);
                acc.x += (v0.x + v1.x) + (v2.x + v3.x);
                acc.y += (v0.y + v1.y) + (v2.y + v3.y);
            }
            for (; k < cnt; k++) {
                int s = __shfl_sync(0xffffffffu, myidx, k);
                float2 v = __half22float2(hs2[s * 32 + lane]);
                acc.x += v.x; acc.y += v.y;
            }
        }
        float dv = g_dinv[node];
        float ox = fmaxf(fmaf(acc.x * dv, scx, shx), 0.f);
        float oy = fmaxf(fmaf(acc.y * dv, scy, shy), 0.f);
        *(float2*)(sxn + nl * 66 + j) = make_float2(ox, oy);
    }
    __syncthreads();

    // phase 2: GEMM2
    int c0 = warp * 8;
    int n = nbase + lane;
    const float* xr = sxn + lane * 66;
    unsigned long long acc[8];
#pragma unroll
    for (int c = 0; c < 8; c++) acc[c] = 0ull;
#pragma unroll 8
    for (int kp = 0; kp < 32; kp++) {
        unsigned long long xx = *(const unsigned long long*)(xr + 2 * kp);
#pragma unroll
        for (int c = 0; c < 8; c++) {
            unsigned long long wv = *(const unsigned long long*)(swk + (c0 + c) * 34 + kp);
            asm("fma.rn.f32x2 %0, %1, %2, %0;" : "+l"(acc[c]) : "l"(xx), "l"(wv));
        }
    }
    {
        float dv = g_dinv[n];
        float r[8];
#pragma unroll
        for (int c = 0; c < 8; c++) {
            float lo, hi;
            asm("mov.b64 {%0,%1}, %2;" : "=f"(lo), "=f"(hi) : "l"(acc[c]));
            r[c] = (lo + hi) * dv;
        }
        uint4 o;
        o.x = pack_half2(r[0], r[1]);
        o.y = pack_half2(r[2], r[3]);
        o.z = pack_half2(r[4], r[5]);
        o.w = pack_half2(r[6], r[7]);
        *(uint4*)((__half*)g_hsh2 + n * 64 + c0) = o;
    }
}

// ---------------- gather layer 3 + FUSED POOLING (reads hsh2) ----------------
__global__ void __launch_bounds__(256) k_gather2(
        const int* __restrict__ bidx,
        const float* __restrict__ b, const float* __restrict__ gm,
        const float* __restrict__ be, const float* __restrict__ rm,
        const float* __restrict__ rv) {
    __shared__ float sval[8][64];
    __shared__ int   sgid[8];
    int lane = threadIdx.x & 31;
    int w = threadIdx.x >> 5;
    int node = blockIdx.x * 8 + w;

    int j = lane * 2;
    float scx = gm[j] * rsqrtf(rv[j] + BN_EPS);
    float scy = gm[j + 1] * rsqrtf(rv[j + 1] + BN_EPS);
    float shx = (b[j] - rm[j]) * scx + be[j];
    float shy = (b[j + 1] - rm[j + 1]) * scy + be[j + 1];

    const __half2* __restrict__ hs2 = g_hsh2;
    float2 acc = __half22float2(hs2[node * 32 + lane]);

    int beg = g_rowptr[node];
    int m = g_rowend[node] - beg;
    const int* __restrict__ idx = g_csrsrc + beg;

    for (int base = 0; base < m; base += 32) {
        int rem = m - base;
        int cnt = (rem < 32) ? rem : 32;
        int myidx = (lane < cnt) ? idx[base + lane] : 0;
        int k = 0;
        for (; k + 4 <= cnt; k += 4) {
            int s0 = __shfl_sync(0xffffffffu, myidx, k);
            int s1 = __shfl_sync(0xffffffffu, myidx, k + 1);
            int s2 = __shfl_sync(0xffffffffu, myidx, k + 2);
            int s3 = __shfl_sync(0xffffffffu, myidx, k + 3);
            float2 v0 = __half22float2(hs2[s0 * 32 + lane]);
            float2 v1 = __half22float2(hs2[s1 * 32 + lane]);
            float2 v2 = __half22float2(hs2[s2 * 32 + lane]);
            float2 v3 = __half22float2(hs2[s3 * 32 + lane]);
            acc.x += (v0.x + v1.x) + (v2.x + v3.x);
            acc.y += (v0.y + v1.y) + (v2.y + v3.y);
        }
        for (; k < cnt; k++) {
            int s = __shfl_sync(0xffffffffu, myidx, k);
            float2 v = __half22float2(hs2[s * 32 + lane]);
            acc.x += v.x; acc.y += v.y;
        }
    }

    float dv = g_dinv[node];
    sval[w][j]     = fmaxf(fmaf(acc.x * dv, scx, shx), 0.f);
    sval[w][j + 1] = fmaxf(fmaf(acc.y * dv, scy, shy), 0.f);
    if (lane == 0) sgid[w] = bidx[node];
    __syncthreads();

    int gid = sgid[w];
    bool leader = (w == 0) || (sgid[w - 1] != gid);
    if (leader) {
        float sx = 0.f, sy = 0.f, mxx = 0.f, mxy = 0.f;
        int c = 0;
        for (int s2 = w; s2 < 8 && sgid[s2] == gid; s2++) {
            float vx = sval[s2][j], vy = sval[s2][j + 1];
            sx += vx; sy += vy;
            mxx = fmaxf(mxx, vx); mxy = fmaxf(mxy, vy);
            c++;
        }
        atomicAdd(&g_gsum[gid * 64 + j], sx);
        atomicAdd(&g_gsum[gid * 64 + j + 1], sy);
        atomicMax(&g_gmax[gid * 64 + j], __float_as_int(mxx));
        atomicMax(&g_gmax[gid * 64 + j + 1], __float_as_int(mxy));
        if (lane == 0) atomicAdd(&g_gcnt[gid], (float)c);
    }
}

// ---------------- MLP head (+ cleanup of pooling accumulators) ----------------
__global__ void k_mlp(const float* __restrict__ mW1, const float* __restrict__ mb1,
                      const float* __restrict__ mW2, const float* __restrict__ mb2,
                      const float* __restrict__ mW3, const float* __restrict__ mb3,
                      float* __restrict__ out) {
    __shared__ float xg[128];
    __shared__ float h1[32];
    __shared__ float h2[16];
    int g = blockIdx.x;
    int t = threadIdx.x;                // 32 threads
    float cnt = fmaxf(g_gcnt[g], 1.f);
    for (int j = t; j < 64; j += 32) {
        xg[j]      = g_gsum[g * 64 + j] / cnt;
        xg[64 + j] = __int_as_float(g_gmax[g * 64 + j]);
    }
    __syncthreads();
    for (int j = t; j < 64; j += 32) {
        g_gsum[g * 64 + j] = 0.f;
        g_gmax[g * 64 + j] = 0;
    }
    if (t == 0) g_gcnt[g] = 0.f;
    {
        float acc = mb1[t];
        for (int k = 0; k < 128; k++) acc += xg[k] * mW1[k * 32 + t];
        h1[t] = fmaxf(acc, 0.f);
    }
    __syncthreads();
    if (t < 16) {
        float acc = mb2[t];
        for (int k = 0; k < 32; k++) acc += h1[k] * mW2[k * 16 + t];
        h2[t] = fmaxf(acc, 0.f);
    }
    __syncthreads();
    if (t == 0) {
        float acc = mb3[0];
        for (int k = 0; k < 16; k++) acc += h2[k] * mW3[k];
        out[g] = acc;
    }
}

extern "C" void kernel_launch(void* const* d_in, const int* in_sizes, int n_in,
                              void* d_out, int out_size) {
    const float* x    = (const float*)d_in[0];
    const int*   ei   = (const int*)  d_in[1];
    const int*   bidx = (const int*)  d_in[2];
    const float* W[3]  = {(const float*)d_in[3],  (const float*)d_in[9],  (const float*)d_in[15]};
    const float* b[3]  = {(const float*)d_in[4],  (const float*)d_in[10], (const float*)d_in[16]};
    const float* gm[3] = {(const float*)d_in[5],  (const float*)d_in[11], (const float*)d_in[17]};
    const float* be[3] = {(const float*)d_in[6],  (const float*)d_in[12], (const float*)d_in[18]};
    const float* rm[3] = {(const float*)d_in[7],  (const float*)d_in[13], (const float*)d_in[19]};
    const float* rv[3] = {(const float*)d_in[8],  (const float*)d_in[14], (const float*)d_in[20]};
    const float* mW1 = (const float*)d_in[21];
    const float* mb1 = (const float*)d_in[22];
    const float* mW2 = (const float*)d_in[23];
    const float* mb2 = (const float*)d_in[24];
    const float* mW3 = (const float*)d_in[25];
    const float* mb3 = (const float*)d_in[26];
    float* out = (float*)d_out;

    const int T = 256;
    int deg4Blocks = (EE / 4 + T - 1) / T;
    int nBlocks    = (NN + T - 1) / T;
    int fuseBlocks = NN / 32;           // NN % 32 == 0
    int gatBlocks  = NN / 8;            // NN % 8 == 0

    k_deg<<<deg4Blocks, T>>>(ei);
    k_alloc<<<nBlocks, T>>>(x);
    k_csr<<<deg4Blocks, T>>>(ei);

    k_l0mm1<<<fuseBlocks, T>>>(W[0], b[0], gm[0], be[0], rm[0], rv[0], W[1]);
    k_g1mm2<<<fuseBlocks, T>>>(b[1], gm[1], be[1], rm[1], rv[1], W[2]);
    k_gather2<<<gatBlocks, T>>>(bidx, b[2], gm[2], be[2], rm[2], rv[2]);

    k_mlp<<<GG, 32>>>(mW1, mb1, mW2, mb2, mW3, mb3, out);
}

// round 12
// speedup vs baseline: 1.2043x; 1.0160x over previous
#include <cuda_runtime.h>
#include <cuda_fp16.h>
#include <cuda_bf16.h>

#define NN 100000
#define EE 1600000
#define GG 256
#define HH 64
#define BN_EPS 1e-5f

// ---------------- scratch (device globals; zero-initialized at load) ----------------
__device__ int     g_deg[NN];          // re-zeroed by k_csr each run
__device__ int     g_total;            // re-zeroed by k_csr each run
__device__ float   g_dinv[NN];
__device__ float4  g_xs[NN];           // dinv * x (3-wide, w=0)
__device__ __half2 g_hsh[NN * 32];     // layer-1 hs (fp16)
__device__ __half2 g_hsh2[NN * 32];    // layer-2 hs (fp16)
__device__ int     g_rowptr[NN];
__device__ int     g_rowend[NN];
__device__ int     g_cursor[NN];
__device__ int     g_csrsrc[EE];
__device__ float   g_gsum[GG * HH];    // re-zeroed by k_mlp each run
__device__ int     g_gmax[GG * HH];    // re-zeroed by k_mlp each run
__device__ float   g_gcnt[GG];         // re-zeroed by k_mlp each run

__device__ __forceinline__ unsigned pack_half2(float a, float b) {
    __half2 h = __float22half2_rn(make_float2(a, b));
    return reinterpret_cast<unsigned&>(h);
}

// ---------------- degree histogram (by dst), 4 edges/thread ----------------
__global__ void k_deg(const int* __restrict__ ei) {
    int i = blockIdx.x * blockDim.x + threadIdx.x;
    if (i < EE / 4) {
        int4 d = ((const int4*)(ei + EE))[i];
        atomicAdd(&g_deg[d.x], 1);
        atomicAdd(&g_deg[d.y], 1);
        atomicAdd(&g_deg[d.z], 1);
        atomicAdd(&g_deg[d.w], 1);
    }
}

// ---------------- CSR slot allocation: warp-aggregated atomic, no scan ----------------
__global__ void k_alloc(const float* __restrict__ x) {
    int i = blockIdx.x * blockDim.x + threadIdx.x;
    int lane = threadIdx.x & 31;
    int d = (i < NN) ? g_deg[i] : 0;
    int incl = d;
#pragma unroll
    for (int off = 1; off < 32; off <<= 1) {
        int v = __shfl_up_sync(0xffffffffu, incl, off);
        if (lane >= off) incl += v;
    }
    int total = __shfl_sync(0xffffffffu, incl, 31);
    int base = 0;
    if (lane == 31) base = atomicAdd(&g_total, total);
    base = __shfl_sync(0xffffffffu, base, 31);
    int excl = base + incl - d;
    if (i < NN) {
        g_rowptr[i] = excl;
        g_rowend[i] = excl + d;
        g_cursor[i] = excl;
        float dv = rsqrtf((float)d + 1.0f);
        g_dinv[i] = dv;
        g_xs[i] = make_float4(x[i * 3] * dv, x[i * 3 + 1] * dv, x[i * 3 + 2] * dv, 0.f);
    }
}

// ---------------- CSR fill, 4 edges/thread (+ cleanup of deg/total) ----------------
__global__ void k_csr(const int* __restrict__ ei) {
    int i = blockIdx.x * blockDim.x + threadIdx.x;
    if (i < NN / 4) ((int4*)g_deg)[i] = make_int4(0, 0, 0, 0);
    if (i == 0) g_total = 0;
    if (i < EE / 4) {
        int4 s = ((const int4*)ei)[i];
        int4 d = ((const int4*)(ei + EE))[i];
        g_csrsrc[atomicAdd(&g_cursor[d.x], 1)] = s.x;
        g_csrsrc[atomicAdd(&g_cursor[d.y], 1)] = s.y;
        g_csrsrc[atomicAdd(&g_cursor[d.z], 1)] = s.z;
        g_csrsrc[atomicAdd(&g_cursor[d.w], 1)] = s.w;
    }
}

// ============ FUSED layer0 + GEMM1: gather3 -> GEMM0+BN+ReLU -> GEMM1 -> hsh1 ============
// Block = 32 nodes (NN % 32 == 0), 256 threads.
// Phase 1a: 8 sub-lanes per node (4 nodes per warp IN PARALLEL), shfl_xor reduce.
// Phase 1b: GEMM0+BN+ReLU from smem aggregates, 8 cols/thread.
// Phase 2:  GEMM1 crossbar-minimal f32x2 (lane = node, warp = 8 cols).
__global__ void __launch_bounds__(256) k_l0mm1(
        const float* __restrict__ W0,
        const float* __restrict__ b, const float* __restrict__ gm,
        const float* __restrict__ be, const float* __restrict__ rm,
        const float* __restrict__ rv,
        const float* __restrict__ W1) {
    __shared__ float  sxn[32 * 66];    // post-BN/ReLU x rows, stride 66
    __shared__ float2 swk[64 * 34];    // W1 k-pairs: [c][kp]
    __shared__ float  sW0[192];
    __shared__ float  sbn_sc[64], sbn_sh[64];
    __shared__ float  sxa[32][3];      // aggregated (dinv-scaled) input features
    int t = threadIdx.x;
    int lane = t & 31, warp = t >> 5;
    int nbase = blockIdx.x * 32;

    if (t < 192) sW0[t] = W0[t];
    if (t < 64) {
        float sc = gm[t] * rsqrtf(rv[t] + BN_EPS);
        sbn_sc[t] = sc;
        sbn_sh[t] = (b[t] - rm[t]) * sc + be[t];
    }
#pragma unroll
    for (int i = t; i < 2048; i += 256) {
        int kp = i >> 6, c = i & 63;
        swk[c * 34 + kp] = make_float2(W1[(2 * kp) * 64 + c], W1[(2 * kp + 1) * 64 + c]);
    }

    // phase 1a: parallel gather, 8 sub-lanes per node
    {
        int nl = warp * 4 + (lane >> 3);     // 0..31
        int sub = lane & 7;
        int node = nbase + nl;
        int beg = g_rowptr[node], end = g_rowend[node];
        const int* __restrict__ idx = g_csrsrc;
        float ax = 0.f, ay = 0.f, az = 0.f;
        for (int k = beg + sub; k < end; k += 8) {
            float4 a = g_xs[idx[k]];
            ax += a.x; ay += a.y; az += a.z;
        }
#pragma unroll
        for (int off = 1; off < 8; off <<= 1) {
            ax += __shfl_xor_sync(0xffffffffu, ax, off);
            ay += __shfl_xor_sync(0xffffffffu, ay, off);
            az += __shfl_xor_sync(0xffffffffu, az, off);
        }
        if (sub == 0) {
            float4 self = g_xs[node];
            float dv = g_dinv[node];
            sxa[nl][0] = (ax + self.x) * dv;
            sxa[nl][1] = (ay + self.y) * dv;
            sxa[nl][2] = (az + self.z) * dv;
        }
    }
    __syncthreads();

    // phase 1b: GEMM0 + BN + ReLU -> sxn ; thread = (node t>>3, 8 cols (t&7)*8)
    {
        int nl = t >> 3;
        int q8 = (t & 7) * 8;
        float a0 = sxa[nl][0], a1 = sxa[nl][1], a2 = sxa[nl][2];
        float* dst = sxn + nl * 66 + q8;
#pragma unroll
        for (int c = 0; c < 8; c++) {
            int jc = q8 + c;
            float v = a0 * sW0[jc] + a1 * sW0[64 + jc] + a2 * sW0[128 + jc];
            dst[c] = fmaxf(fmaf(v, sbn_sc[jc], sbn_sh[jc]), 0.f);
        }
    }
    __syncthreads();

    // phase 2: GEMM1 (crossbar-minimal), lane = node, warp = 8 cols
    int c0 = warp * 8;
    int n = nbase + lane;
    const float* xr = sxn + lane * 66;
    unsigned long long acc[8];
#pragma unroll
    for (int c = 0; c < 8; c++) acc[c] = 0ull;
#pragma unroll 8
    for (int kp = 0; kp < 32; kp++) {
        unsigned long long xx = *(const unsigned long long*)(xr + 2 * kp);
#pragma unroll
        for (int c = 0; c < 8; c++) {
            unsigned long long wv = *(const unsigned long long*)(swk + (c0 + c) * 34 + kp);
            asm("fma.rn.f32x2 %0, %1, %2, %0;" : "+l"(acc[c]) : "l"(xx), "l"(wv));
        }
    }
    {
        float dv = g_dinv[n];
        float r[8];
#pragma unroll
        for (int c = 0; c < 8; c++) {
            float lo, hi;
            asm("mov.b64 {%0,%1}, %2;" : "=f"(lo), "=f"(hi) : "l"(acc[c]));
            r[c] = (lo + hi) * dv;
        }
        uint4 o;
        o.x = pack_half2(r[0], r[1]);
        o.y = pack_half2(r[2], r[3]);
        o.z = pack_half2(r[4], r[5]);
        o.w = pack_half2(r[6], r[7]);
        *(uint4*)((__half*)g_hsh + n * 64 + c0) = o;
    }
}

// ============ FUSED gather(l1) + GEMM2: gather hsh1 -> BN+ReLU -> GEMM2 -> hsh2 ============
__global__ void __launch_bounds__(256) k_g1mm2(
        const float* __restrict__ b, const float* __restrict__ gm,
        const float* __restrict__ be, const float* __restrict__ rm,
        const float* __restrict__ rv,
        const float* __restrict__ W2) {
    __shared__ float  sxn[32 * 66];
    __shared__ float2 swk[64 * 34];
    int t = threadIdx.x;
    int lane = t & 31, warp = t >> 5;
    int nbase = blockIdx.x * 32;

#pragma unroll
    for (int i = t; i < 2048; i += 256) {
        int kp = i >> 6, c = i & 63;
        swk[c * 34 + kp] = make_float2(W2[(2 * kp) * 64 + c], W2[(2 * kp + 1) * 64 + c]);
    }

    int j = lane * 2;
    float scx = gm[j] * rsqrtf(rv[j] + BN_EPS);
    float scy = gm[j + 1] * rsqrtf(rv[j + 1] + BN_EPS);
    float shx = (b[j] - rm[j]) * scx + be[j];
    float shy = (b[j + 1] - rm[j + 1]) * scy + be[j + 1];

    const __half2* __restrict__ hs2 = g_hsh;

    // phase 1: each warp gathers 4 nodes (lane owns cols j, j+1)
#pragma unroll
    for (int i = 0; i < 4; i++) {
        int nl = warp * 4 + i;
        int node = nbase + nl;
        float2 acc = __half22float2(hs2[node * 32 + lane]);   // self-loop term
        int beg = g_rowptr[node];
        int m = g_rowend[node] - beg;
        const int* __restrict__ idx = g_csrsrc + beg;
        for (int base = 0; base < m; base += 32) {
            int rem = m - base;
            int cnt = (rem < 32) ? rem : 32;
            int myidx = (lane < cnt) ? idx[base + lane] : 0;
            int k = 0;
            for (; k + 4 <= cnt; k += 4) {
                int s0 = __shfl_sync(0xffffffffu, myidx, k);
                int s1 = __shfl_sync(0xffffffffu, myidx, k + 1);
                int s2 = __shfl_sync(0xffffffffu, myidx, k + 2);
                int s3 = __shfl_sync(0xffffffffu, myidx, k + 3);
                float2 v0 = __half22float2(hs2[s0 * 32 + lane]);
                float2 v1 = __half22float2(hs2[s1 * 32 + lane]);
                float2 v2 = __half22float2(hs2[s2 * 32 + lane]);
                float2 v3 = __half22float2(hs2[s3 * 32 + lane]);
                acc.x += (v0.x + v1.x) + (v2.x + v3.x);
                acc.y += (v0.y + v1.y) + (v2.y + v3.y);
            }
            for (; k < cnt; k++) {
                int s = __shfl_sync(0xffffffffu, myidx, k);
                float2 v = __half22float2(hs2[s * 32 + lane]);
                acc.x += v.x; acc.y += v.y;
            }
        }
        float dv = g_dinv[node];
        float ox = fmaxf(fmaf(acc.x * dv, scx, shx), 0.f);
        float oy = fmaxf(fmaf(acc.y * dv, scy, shy), 0.f);
        *(float2*)(sxn + nl * 66 + j) = make_float2(ox, oy);
    }
    __syncthreads();

    // phase 2: GEMM2
    int c0 = warp * 8;
    int n = nbase + lane;
    const float* xr = sxn + lane * 66;
    unsigned long long acc[8];
#pragma unroll
    for (int c = 0; c < 8; c++) acc[c] = 0ull;
#pragma unroll 8
    for (int kp = 0; kp < 32; kp++) {
        unsigned long long xx = *(const unsigned long long*)(xr + 2 * kp);
#pragma unroll
        for (int c = 0; c < 8; c++) {
            unsigned long long wv = *(const unsigned long long*)(swk + (c0 + c) * 34 + kp);
            asm("fma.rn.f32x2 %0, %1, %2, %0;" : "+l"(acc[c]) : "l"(xx), "l"(wv));
        }
    }
    {
        float dv = g_dinv[n];
        float r[8];
#pragma unroll
        for (int c = 0; c < 8; c++) {
            float lo, hi;
            asm("mov.b64 {%0,%1}, %2;" : "=f"(lo), "=f"(hi) : "l"(acc[c]));
            r[c] = (lo + hi) * dv;
        }
        uint4 o;
        o.x = pack_half2(r[0], r[1]);
        o.y = pack_half2(r[2], r[3]);
        o.z = pack_half2(r[4], r[5]);
        o.w = pack_half2(r[6], r[7]);
        *(uint4*)((__half*)g_hsh2 + n * 64 + c0) = o;
    }
}

// ---------------- gather layer 3 + FUSED POOLING (reads hsh2) ----------------
__global__ void __launch_bounds__(256) k_gather2(
        const int* __restrict__ bidx,
        const float* __restrict__ b, const float* __restrict__ gm,
        const float* __restrict__ be, const float* __restrict__ rm,
        const float* __restrict__ rv) {
    __shared__ float sval[8][64];
    __shared__ int   sgid[8];
    int lane = threadIdx.x & 31;
    int w = threadIdx.x >> 5;
    int node = blockIdx.x * 8 + w;

    int j = lane * 2;
    float scx = gm[j] * rsqrtf(rv[j] + BN_EPS);
    float scy = gm[j + 1] * rsqrtf(rv[j + 1] + BN_EPS);
    float shx = (b[j] - rm[j]) * scx + be[j];
    float shy = (b[j + 1] - rm[j + 1]) * scy + be[j + 1];

    const __half2* __restrict__ hs2 = g_hsh2;
    float2 acc = __half22float2(hs2[node * 32 + lane]);

    int beg = g_rowptr[node];
    int m = g_rowend[node] - beg;
    const int* __restrict__ idx = g_csrsrc + beg;

    for (int base = 0; base < m; base += 32) {
        int rem = m - base;
        int cnt = (rem < 32) ? rem : 32;
        int myidx = (lane < cnt) ? idx[base + lane] : 0;
        int k = 0;
        for (; k + 4 <= cnt; k += 4) {
            int s0 = __shfl_sync(0xffffffffu, myidx, k);
            int s1 = __shfl_sync(0xffffffffu, myidx, k + 1);
            int s2 = __shfl_sync(0xffffffffu, myidx, k + 2);
            int s3 = __shfl_sync(0xffffffffu, myidx, k + 3);
            float2 v0 = __half22float2(hs2[s0 * 32 + lane]);
            float2 v1 = __half22float2(hs2[s1 * 32 + lane]);
            float2 v2 = __half22float2(hs2[s2 * 32 + lane]);
            float2 v3 = __half22float2(hs2[s3 * 32 + lane]);
            acc.x += (v0.x + v1.x) + (v2.x + v3.x);
            acc.y += (v0.y + v1.y) + (v2.y + v3.y);
        }
        for (; k < cnt; k++) {
            int s = __shfl_sync(0xffffffffu, myidx, k);
            float2 v = __half22float2(hs2[s * 32 + lane]);
            acc.x += v.x; acc.y += v.y;
        }
    }

    float dv = g_dinv[node];
    sval[w][j]     = fmaxf(fmaf(acc.x * dv, scx, shx), 0.f);
    sval[w][j + 1] = fmaxf(fmaf(acc.y * dv, scy, shy), 0.f);
    if (lane == 0) sgid[w] = bidx[node];
    __syncthreads();

    int gid = sgid[w];
    bool leader = (w == 0) || (sgid[w - 1] != gid);
    if (leader) {
        float sx = 0.f, sy = 0.f, mxx = 0.f, mxy = 0.f;
        int c = 0;
        for (int s2 = w; s2 < 8 && sgid[s2] == gid; s2++) {
            float vx = sval[s2][j], vy = sval[s2][j + 1];
            sx += vx; sy += vy;
            mxx = fmaxf(mxx, vx); mxy = fmaxf(mxy, vy);
            c++;
        }
        atomicAdd(&g_gsum[gid * 64 + j], sx);
        atomicAdd(&g_gsum[gid * 64 + j + 1], sy);
        atomicMax(&g_gmax[gid * 64 + j], __float_as_int(mxx));
        atomicMax(&g_gmax[gid * 64 + j + 1], __float_as_int(mxy));
        if (lane == 0) atomicAdd(&g_gcnt[gid], (float)c);
    }
}

// ---------------- MLP head (+ cleanup of pooling accumulators) ----------------
__global__ void k_mlp(const float* __restrict__ mW1, const float* __restrict__ mb1,
                      const float* __restrict__ mW2, const float* __restrict__ mb2,
                      const float* __restrict__ mW3, const float* __restrict__ mb3,
                      float* __restrict__ out) {
    __shared__ float xg[128];
    __shared__ float h1[32];
    __shared__ float h2[16];
    int g = blockIdx.x;
    int t = threadIdx.x;                // 32 threads
    float cnt = fmaxf(g_gcnt[g], 1.f);
    for (int j = t; j < 64; j += 32) {
        xg[j]      = g_gsum[g * 64 + j] / cnt;
        xg[64 + j] = __int_as_float(g_gmax[g * 64 + j]);
    }
    __syncthreads();
    for (int j = t; j < 64; j += 32) {
        g_gsum[g * 64 + j] = 0.f;
        g_gmax[g * 64 + j] = 0;
    }
    if (t == 0) g_gcnt[g] = 0.f;
    {
        float acc = mb1[t];
        for (int k = 0; k < 128; k++) acc += xg[k] * mW1[k * 32 + t];
        h1[t] = fmaxf(acc, 0.f);
    }
    __syncthreads();
    if (t < 16) {
        float acc = mb2[t];
        for (int k = 0; k < 32; k++) acc += h1[k] * mW2[k * 16 + t];
        h2[t] = fmaxf(acc, 0.f);
    }
    __syncthreads();
    if (t == 0) {
        float acc = mb3[0];
        for (int k = 0; k < 16; k++) acc += h2[k] * mW3[k];
        out[g] = acc;
    }
}

extern "C" void kernel_launch(void* const* d_in, const int* in_sizes, int n_in,
                              void* d_out, int out_size) {
    const float* x    = (const float*)d_in[0];
    const int*   ei   = (const int*)  d_in[1];
    const int*   bidx = (const int*)  d_in[2];
    const float* W[3]  = {(const float*)d_in[3],  (const float*)d_in[9],  (const float*)d_in[15]};
    const float* b[3]  = {(const float*)d_in[4],  (const float*)d_in[10], (const float*)d_in[16]};
    const float* gm[3] = {(const float*)d_in[5],  (const float*)d_in[11], (const float*)d_in[17]};
    const float* be[3] = {(const float*)d_in[6],  (const float*)d_in[12], (const float*)d_in[18]};
    const float* rm[3] = {(const float*)d_in[7],  (const float*)d_in[13], (const float*)d_in[19]};
    const float* rv[3] = {(const float*)d_in[8],  (const float*)d_in[14], (const float*)d_in[20]};
    const float* mW1 = (const float*)d_in[21];
    const float* mb1 = (const float*)d_in[22];
    const float* mW2 = (const float*)d_in[23];
    const float* mb2 = (const float*)d_in[24];
    const float* mW3 = (const float*)d_in[25];
    const float* mb3 = (const float*)d_in[26];
    float* out = (float*)d_out;

    const int T = 256;
    int deg4Blocks = (EE / 4 + T - 1) / T;
    int nBlocks    = (NN + T - 1) / T;
    int fuseBlocks = NN / 32;           // NN % 32 == 0
    int gatBlocks  = NN / 8;            // NN % 8 == 0

    k_deg<<<deg4Blocks, T>>>(ei);
    k_alloc<<<nBlocks, T>>>(x);
    k_csr<<<deg4Blocks, T>>>(ei);

    k_l0mm1<<<fuseBlocks, T>>>(W[0], b[0], gm[0], be[0], rm[0], rv[0], W[1]);
    k_g1mm2<<<fuseBlocks, T>>>(b[1], gm[1], be[1], rm[1], rv[1], W[2]);
    k_gather2<<<gatBlocks, T>>>(bidx, b[2], gm[2], be[2], rm[2], rv[2]);

    k_mlp<<<GG, 32>>>(mW1, mb1, mW2, mb2, mW3, mb3, out);
}

// round 13
// speedup vs baseline: 1.2193x; 1.0125x over previous
#include <cuda_runtime.h>
#include <cuda_fp16.h>
#include <cuda_bf16.h>

#define NN 100000
#define EE 1600000
#define GG 256
#define HH 64
#define BN_EPS 1e-5f

// ---------------- scratch (device globals; zero-initialized at load) ----------------
__device__ int     g_deg[NN];          // re-zeroed by k_csr each run
__device__ int     g_total;            // re-zeroed by k_csr each run
__device__ float   g_dinv[NN];
__device__ float4  g_xs[NN];           // dinv * x (3-wide, w=0)
__device__ __half2 g_hsh[NN * 32];     // layer-1 hs (fp16)
__device__ __half2 g_hsh2[NN * 32];    // layer-2 hs (fp16)
__device__ int     g_rowptr[NN];
__device__ int     g_rowend[NN];
__device__ int     g_cursor[NN];
__device__ int     g_csrsrc[EE];
__device__ float   g_gsum[GG * HH];    // re-zeroed by k_mlp each run
__device__ int     g_gmax[GG * HH];    // re-zeroed by k_mlp each run
__device__ float   g_gcnt[GG];         // re-zeroed by k_mlp each run

__device__ __forceinline__ unsigned pack_half2(float a, float b) {
    __half2 h = __float22half2_rn(make_float2(a, b));
    return reinterpret_cast<unsigned&>(h);
}
__device__ __forceinline__ unsigned long long pack_f2(float a, float b) {
    unsigned long long r;
    asm("mov.b64 %0, {%1,%2};" : "=l"(r) : "f"(a), "f"(b));
    return r;
}

// ---------------- degree histogram (by dst), 4 edges/thread ----------------
__global__ void k_deg(const int* __restrict__ ei) {
    int i = blockIdx.x * blockDim.x + threadIdx.x;
    if (i < EE / 4) {
        int4 d = ((const int4*)(ei + EE))[i];
        atomicAdd(&g_deg[d.x], 1);
        atomicAdd(&g_deg[d.y], 1);
        atomicAdd(&g_deg[d.z], 1);
        atomicAdd(&g_deg[d.w], 1);
    }
}

// ---------------- CSR slot allocation: warp-aggregated atomic, no scan ----------------
__global__ void k_alloc(const float* __restrict__ x) {
    int i = blockIdx.x * blockDim.x + threadIdx.x;
    int lane = threadIdx.x & 31;
    int d = (i < NN) ? g_deg[i] : 0;
    int incl = d;
#pragma unroll
    for (int off = 1; off < 32; off <<= 1) {
        int v = __shfl_up_sync(0xffffffffu, incl, off);
        if (lane >= off) incl += v;
    }
    int total = __shfl_sync(0xffffffffu, incl, 31);
    int base = 0;
    if (lane == 31) base = atomicAdd(&g_total, total);
    base = __shfl_sync(0xffffffffu, base, 31);
    int excl = base + incl - d;
    if (i < NN) {
        g_rowptr[i] = excl;
        g_rowend[i] = excl + d;
        g_cursor[i] = excl;
        float dv = rsqrtf((float)d + 1.0f);
        g_dinv[i] = dv;
        g_xs[i] = make_float4(x[i * 3] * dv, x[i * 3 + 1] * dv, x[i * 3 + 2] * dv, 0.f);
    }
}

// ---------------- CSR fill, 4 edges/thread (+ cleanup of deg/total) ----------------
__global__ void k_csr(const int* __restrict__ ei) {
    int i = blockIdx.x * blockDim.x + threadIdx.x;
    if (i < NN / 4) ((int4*)g_deg)[i] = make_int4(0, 0, 0, 0);
    if (i == 0) g_total = 0;
    if (i < EE / 4) {
        int4 s = ((const int4*)ei)[i];
        int4 d = ((const int4*)(ei + EE))[i];
        g_csrsrc[atomicAdd(&g_cursor[d.x], 1)] = s.x;
        g_csrsrc[atomicAdd(&g_cursor[d.y], 1)] = s.y;
        g_csrsrc[atomicAdd(&g_cursor[d.z], 1)] = s.z;
        g_csrsrc[atomicAdd(&g_cursor[d.w], 1)] = s.w;
    }
}

#define XSTRIDE 68   // floats per sxn row: 272 B, 16B-aligned, conflict-free LDS.128

// ============ FUSED layer0 + GEMM1 ============
// Block = 64 nodes, 512 threads (16 warps).
__global__ void __launch_bounds__(512) k_l0mm1(
        const float* __restrict__ W0,
        const float* __restrict__ b, const float* __restrict__ gm,
        const float* __restrict__ be, const float* __restrict__ rm,
        const float* __restrict__ rv,
        const float* __restrict__ W1) {
    __shared__ __align__(16) float sxn[64 * XSTRIDE];
    __shared__ float4 swk4[64 * 17];     // [c][kp2]: (W[4kp2..4kp2+3][c]), stride 17
    __shared__ float  sW0[192];
    __shared__ float  sbn_sc[64], sbn_sh[64];
    __shared__ float  sxa[64][3];
    int t = threadIdx.x;
    int lane = t & 31, warp = t >> 5;
    int nbase = blockIdx.x * 64;

    if (t < 192) sW0[t] = W0[t];
    if (t < 64) {
        float sc = gm[t] * rsqrtf(rv[t] + BN_EPS);
        sbn_sc[t] = sc;
        sbn_sh[t] = (b[t] - rm[t]) * sc + be[t];
    }
#pragma unroll
    for (int i = t; i < 1024; i += 512) {
        int kp2 = i >> 6, c = i & 63;
        swk4[c * 17 + kp2] = make_float4(W1[(4 * kp2) * 64 + c],
                                         W1[(4 * kp2 + 1) * 64 + c],
                                         W1[(4 * kp2 + 2) * 64 + c],
                                         W1[(4 * kp2 + 3) * 64 + c]);
    }

    // phase 1a: parallel gather, 8 sub-lanes per node (4 nodes/warp in parallel)
    {
        int nl = warp * 4 + (lane >> 3);     // 0..63
        int sub = lane & 7;
        int node = nbase + nl;
        int beg = 0, end = 0;
        if (node < NN) { beg = g_rowptr[node]; end = g_rowend[node]; }
        const int* __restrict__ idx = g_csrsrc;
        float ax = 0.f, ay = 0.f, az = 0.f;
        for (int k = beg + sub; k < end; k += 8) {
            float4 a = g_xs[idx[k]];
            ax += a.x; ay += a.y; az += a.z;
        }
#pragma unroll
        for (int off = 1; off < 8; off <<= 1) {
            ax += __shfl_xor_sync(0xffffffffu, ax, off);
            ay += __shfl_xor_sync(0xffffffffu, ay, off);
            az += __shfl_xor_sync(0xffffffffu, az, off);
        }
        if (sub == 0 && node < NN) {
            float4 self = g_xs[node];
            float dv = g_dinv[node];
            sxa[nl][0] = (ax + self.x) * dv;
            sxa[nl][1] = (ay + self.y) * dv;
            sxa[nl][2] = (az + self.z) * dv;
        }
    }
    __syncthreads();

    // phase 1b: GEMM0 + BN + ReLU -> sxn ; thread = (node t>>3, 8 cols (t&7)*8)
    {
        int nl = t >> 3;
        int q8 = (t & 7) * 8;
        if (nbase + nl < NN) {
            float a0 = sxa[nl][0], a1 = sxa[nl][1], a2 = sxa[nl][2];
            float* dst = sxn + nl * XSTRIDE + q8;
#pragma unroll
            for (int c = 0; c < 8; c++) {
                int jc = q8 + c;
                float v = a0 * sW0[jc] + a1 * sW0[64 + jc] + a2 * sW0[128 + jc];
                dst[c] = fmaxf(fmaf(v, sbn_sc[jc], sbn_sh[jc]), 0.f);
            }
        }
    }
    __syncthreads();

    // phase 2: GEMM1. warps 0-7 -> nodes 0-31, warps 8-15 -> nodes 32-63; 8 cols each.
    int nh = warp >> 3;
    int c0 = (warp & 7) * 8;
    int nl = nh * 32 + lane;
    int n = nbase + nl;
    const float* xr = sxn + nl * XSTRIDE;
    unsigned long long acc[8];
#pragma unroll
    for (int c = 0; c < 8; c++) acc[c] = 0ull;
#pragma unroll 4
    for (int kp2 = 0; kp2 < 16; kp2++) {
        float4 xv = *(const float4*)(xr + 4 * kp2);
        unsigned long long x01 = pack_f2(xv.x, xv.y);
        unsigned long long x23 = pack_f2(xv.z, xv.w);
#pragma unroll
        for (int c = 0; c < 8; c++) {
            float4 wv = swk4[(c0 + c) * 17 + kp2];       // broadcast LDS.128
            unsigned long long w01 = pack_f2(wv.x, wv.y);
            unsigned long long w23 = pack_f2(wv.z, wv.w);
            asm("fma.rn.f32x2 %0, %1, %2, %0;" : "+l"(acc[c]) : "l"(x01), "l"(w01));
            asm("fma.rn.f32x2 %0, %1, %2, %0;" : "+l"(acc[c]) : "l"(x23), "l"(w23));
        }
    }
    if (n < NN) {
        float dv = g_dinv[n];
        float r[8];
#pragma unroll
        for (int c = 0; c < 8; c++) {
            float lo, hi;
            asm("mov.b64 {%0,%1}, %2;" : "=f"(lo), "=f"(hi) : "l"(acc[c]));
            r[c] = (lo + hi) * dv;
        }
        uint4 o;
        o.x = pack_half2(r[0], r[1]);
        o.y = pack_half2(r[2], r[3]);
        o.z = pack_half2(r[4], r[5]);
        o.w = pack_half2(r[6], r[7]);
        *(uint4*)((__half*)g_hsh + n * 64 + c0) = o;
    }
}

// ============ FUSED gather(l1) + GEMM2 ============
// Block = 64 nodes, 512 threads (16 warps).
__global__ void __launch_bounds__(512) k_g1mm2(
        const float* __restrict__ b, const float* __restrict__ gm,
        const float* __restrict__ be, const float* __restrict__ rm,
        const float* __restrict__ rv,
        const float* __restrict__ W2) {
    __shared__ __align__(16) float sxn[64 * XSTRIDE];
    __shared__ float4 swk4[64 * 17];
    int t = threadIdx.x;
    int lane = t & 31, warp = t >> 5;
    int nbase = blockIdx.x * 64;

#pragma unroll
    for (int i = t; i < 1024; i += 512) {
        int kp2 = i >> 6, c = i & 63;
        swk4[c * 17 + kp2] = make_float4(W2[(4 * kp2) * 64 + c],
                                         W2[(4 * kp2 + 1) * 64 + c],
                                         W2[(4 * kp2 + 2) * 64 + c],
                                         W2[(4 * kp2 + 3) * 64 + c]);
    }

    int j = lane * 2;
    float scx = gm[j] * rsqrtf(rv[j] + BN_EPS);
    float scy = gm[j + 1] * rsqrtf(rv[j + 1] + BN_EPS);
    float shx = (b[j] - rm[j]) * scx + be[j];
    float shy = (b[j + 1] - rm[j + 1]) * scy + be[j + 1];

    const __half2* __restrict__ hs2 = g_hsh;

    // phase 1: each warp gathers 4 nodes (lane owns cols j, j+1)
#pragma unroll
    for (int i = 0; i < 4; i++) {
        int nl = warp * 4 + i;
        int node = nbase + nl;
        if (node >= NN) break;
        float2 acc = __half22float2(hs2[node * 32 + lane]);   // self-loop term
        int beg = g_rowptr[node];
        int m = g_rowend[node] - beg;
        const int* __restrict__ idx = g_csrsrc + beg;
        for (int base = 0; base < m; base += 32) {
            int rem = m - base;
            int cnt = (rem < 32) ? rem : 32;
            int myidx = (lane < cnt) ? idx[base + lane] : 0;
            int k = 0;
            for (; k + 4 <= cnt; k += 4) {
                int s0 = __shfl_sync(0xffffffffu, myidx, k);
                int s1 = __shfl_sync(0xffffffffu, myidx, k + 1);
                int s2 = __shfl_sync(0xffffffffu, myidx, k + 2);
                int s3 = __shfl_sync(0xffffffffu, myidx, k + 3);
                float2 v0 = __half22float2(hs2[s0 * 32 + lane]);
                float2 v1 = __half22float2(hs2[s1 * 32 + lane]);
                float2 v2 = __half22float2(hs2[s2 * 32 + lane]);
                float2 v3 = __half22float2(hs2[s3 * 32 + lane]);
                acc.x += (v0.x + v1.x) + (v2.x + v3.x);
                acc.y += (v0.y + v1.y) + (v2.y + v3.y);
            }
            for (; k < cnt; k++) {
                int s = __shfl_sync(0xffffffffu, myidx, k);
                float2 v = __half22float2(hs2[s * 32 + lane]);
                acc.x += v.x; acc.y += v.y;
            }
        }
        float dv = g_dinv[node];
        float ox = fmaxf(fmaf(acc.x * dv, scx, shx), 0.f);
        float oy = fmaxf(fmaf(acc.y * dv, scy, shy), 0.f);
        *(float2*)(sxn + nl * XSTRIDE + j) = make_float2(ox, oy);
    }
    __syncthreads();

    // phase 2: GEMM2
    int nh = warp >> 3;
    int c0 = (warp & 7) * 8;
    int nl = nh * 32 + lane;
    int n = nbase + nl;
    const float* xr = sxn + nl * XSTRIDE;
    unsigned long long acc[8];
#pragma unroll
    for (int c = 0; c < 8; c++) acc[c] = 0ull;
#pragma unroll 4
    for (int kp2 = 0; kp2 < 16; kp2++) {
        float4 xv = *(const float4*)(xr + 4 * kp2);
        unsigned long long x01 = pack_f2(xv.x, xv.y);
        unsigned long long x23 = pack_f2(xv.z, xv.w);
#pragma unroll
        for (int c = 0; c < 8; c++) {
            float4 wv = swk4[(c0 + c) * 17 + kp2];
            unsigned long long w01 = pack_f2(wv.x, wv.y);
            unsigned long long w23 = pack_f2(wv.z, wv.w);
            asm("fma.rn.f32x2 %0, %1, %2, %0;" : "+l"(acc[c]) : "l"(x01), "l"(w01));
            asm("fma.rn.f32x2 %0, %1, %2, %0;" : "+l"(acc[c]) : "l"(x23), "l"(w23));
        }
    }
    if (n < NN) {
        float dv = g_dinv[n];
        float r[8];
#pragma unroll
        for (int c = 0; c < 8; c++) {
            float lo, hi;
            asm("mov.b64 {%0,%1}, %2;" : "=f"(lo), "=f"(hi) : "l"(acc[c]));
            r[c] = (lo + hi) * dv;
        }
        uint4 o;
        o.x = pack_half2(r[0], r[1]);
        o.y = pack_half2(r[2], r[3]);
        o.z = pack_half2(r[4], r[5]);
        o.w = pack_half2(r[6], r[7]);
        *(uint4*)((__half*)g_hsh2 + n * 64 + c0) = o;
    }
}

// ---------------- gather layer 3 + FUSED POOLING (reads hsh2) ----------------
__global__ void __launch_bounds__(256) k_gather2(
        const int* __restrict__ bidx,
        const float* __restrict__ b, const float* __restrict__ gm,
        const float* __restrict__ be, const float* __restrict__ rm,
        const float* __restrict__ rv) {
    __shared__ float sval[8][64];
    __shared__ int   sgid[8];
    int lane = threadIdx.x & 31;
    int w = threadIdx.x >> 5;
    int node = blockIdx.x * 8 + w;

    int j = lane * 2;
    float scx = gm[j] * rsqrtf(rv[j] + BN_EPS);
    float scy = gm[j + 1] * rsqrtf(rv[j + 1] + BN_EPS);
    float shx = (b[j] - rm[j]) * scx + be[j];
    float shy = (b[j + 1] - rm[j + 1]) * scy + be[j + 1];

    const __half2* __restrict__ hs2 = g_hsh2;
    float2 acc = __half22float2(hs2[node * 32 + lane]);

    int beg = g_rowptr[node];
    int m = g_rowend[node] - beg;
    const int* __restrict__ idx = g_csrsrc + beg;

    for (int base = 0; base < m; base += 32) {
        int rem = m - base;
        int cnt = (rem < 32) ? rem : 32;
        int myidx = (lane < cnt) ? idx[base + lane] : 0;
        int k = 0;
        for (; k + 4 <= cnt; k += 4) {
            int s0 = __shfl_sync(0xffffffffu, myidx, k);
            int s1 = __shfl_sync(0xffffffffu, myidx, k + 1);
            int s2 = __shfl_sync(0xffffffffu, myidx, k + 2);
            int s3 = __shfl_sync(0xffffffffu, myidx, k + 3);
            float2 v0 = __half22float2(hs2[s0 * 32 + lane]);
            float2 v1 = __half22float2(hs2[s1 * 32 + lane]);
            float2 v2 = __half22float2(hs2[s2 * 32 + lane]);
            float2 v3 = __half22float2(hs2[s3 * 32 + lane]);
            acc.x += (v0.x + v1.x) + (v2.x + v3.x);
            acc.y += (v0.y + v1.y) + (v2.y + v3.y);
        }
        for (; k < cnt; k++) {
            int s = __shfl_sync(0xffffffffu, myidx, k);
            float2 v = __half22float2(hs2[s * 32 + lane]);
            acc.x += v.x; acc.y += v.y;
        }
    }

    float dv = g_dinv[node];
    sval[w][j]     = fmaxf(fmaf(acc.x * dv, scx, shx), 0.f);
    sval[w][j + 1] = fmaxf(fmaf(acc.y * dv, scy, shy), 0.f);
    if (lane == 0) sgid[w] = bidx[node];
    __syncthreads();

    int gid = sgid[w];
    bool leader = (w == 0) || (sgid[w - 1] != gid);
    if (leader) {
        float sx = 0.f, sy = 0.f, mxx = 0.f, mxy = 0.f;
        int c = 0;
        for (int s2 = w; s2 < 8 && sgid[s2] == gid; s2++) {
            float vx = sval[s2][j], vy = sval[s2][j + 1];
            sx += vx; sy += vy;
            mxx = fmaxf(mxx, vx); mxy = fmaxf(mxy, vy);
            c++;
        }
        atomicAdd(&g_gsum[gid * 64 + j], sx);
        atomicAdd(&g_gsum[gid * 64 + j + 1], sy);
        atomicMax(&g_gmax[gid * 64 + j], __float_as_int(mxx));
        atomicMax(&g_gmax[gid * 64 + j + 1], __float_as_int(mxy));
        if (lane == 0) atomicAdd(&g_gcnt[gid], (float)c);
    }
}

// ---------------- MLP head (+ cleanup of pooling accumulators) ----------------
__global__ void k_mlp(const float* __restrict__ mW1, const float* __restrict__ mb1,
                      const float* __restrict__ mW2, const float* __restrict__ mb2,
                      const float* __restrict__ mW3, const float* __restrict__ mb3,
                      float* __restrict__ out) {
    __shared__ float xg[128];
    __shared__ float h1[32];
    __shared__ float h2[16];
    int g = blockIdx.x;
    int t = threadIdx.x;                // 32 threads
    float cnt = fmaxf(g_gcnt[g], 1.f);
    for (int j = t; j < 64; j += 32) {
        xg[j]      = g_gsum[g * 64 + j] / cnt;
        xg[64 + j] = __int_as_float(g_gmax[g * 64 + j]);
    }
    __syncthreads();
    for (int j = t; j < 64; j += 32) {
        g_gsum[g * 64 + j] = 0.f;
        g_gmax[g * 64 + j] = 0;
    }
    if (t == 0) g_gcnt[g] = 0.f;
    {
        float acc = mb1[t];
        for (int k = 0; k < 128; k++) acc += xg[k] * mW1[k * 32 + t];
        h1[t] = fmaxf(acc, 0.f);
    }
    __syncthreads();
    if (t < 16) {
        float acc = mb2[t];
        for (int k = 0; k < 32; k++) acc += h1[k] * mW2[k * 16 + t];
        h2[t] = fmaxf(acc, 0.f);
    }
    __syncthreads();
    if (t == 0) {
        float acc = mb3[0];
        for (int k = 0; k < 16; k++) acc += h2[k] * mW3[k];
        out[g] = acc;
    }
}

extern "C" void kernel_launch(void* const* d_in, const int* in_sizes, int n_in,
                              void* d_out, int out_size) {
    const float* x    = (const float*)d_in[0];
    const int*   ei   = (const int*)  d_in[1];
    const int*   bidx = (const int*)  d_in[2];
    const float* W[3]  = {(const float*)d_in[3],  (const float*)d_in[9],  (const float*)d_in[15]};
    const float* b[3]  = {(const float*)d_in[4],  (const float*)d_in[10], (const float*)d_in[16]};
    const float* gm[3] = {(const float*)d_in[5],  (const float*)d_in[11], (const float*)d_in[17]};
    const float* be[3] = {(const float*)d_in[6],  (const float*)d_in[12], (const float*)d_in[18]};
    const float* rm[3] = {(const float*)d_in[7],  (const float*)d_in[13], (const float*)d_in[19]};
    const float* rv[3] = {(const float*)d_in[8],  (const float*)d_in[14], (const float*)d_in[20]};
    const float* mW1 = (const float*)d_in[21];
    const float* mb1 = (const float*)d_in[22];
    const float* mW2 = (const float*)d_in[23];
    const float* mb2 = (const float*)d_in[24];
    const float* mW3 = (const float*)d_in[25];
    const float* mb3 = (const float*)d_in[26];
    float* out = (float*)d_out;

    const int T = 256;
    int deg4Blocks = (EE / 4 + T - 1) / T;
    int nBlocks    = (NN + T - 1) / T;
    int fuseBlocks = (NN + 63) / 64;
    int gatBlocks  = NN / 8;            // NN % 8 == 0

    k_deg<<<deg4Blocks, T>>>(ei);
    k_alloc<<<nBlocks, T>>>(x);
    k_csr<<<deg4Blocks, T>>>(ei);

    k_l0mm1<<<fuseBlocks, 512>>>(W[0], b[0], gm[0], be[0], rm[0], rv[0], W[1]);
    k_g1mm2<<<fuseBlocks, 512>>>(b[1], gm[1], be[1], rm[1], rv[1], W[2]);
    k_gather2<<<gatBlocks, T>>>(bidx, b[2], gm[2], be[2], rm[2], rv[2]);

    k_mlp<<<GG, 32>>>(mW1, mb1, mW2, mb2, mW3, mb3, out);
}